// round 1
// baseline (speedup 1.0000x reference)
#include <cuda_runtime.h>
#include <math.h>

#define B_  4
#define T_  4096
#define C_  2048
#define HS_ 128

// Scratch for Q/K/V projections (8 MB each) — device globals per harness rules.
__device__ float g_Q[B_ * T_ * HS_];
__device__ float g_K[B_ * T_ * HS_];
__device__ float g_V[B_ * T_ * HS_];

// ---------------------------------------------------------------------------
// Fused QKV projection: out = x @ W, for W in {Wq, Wk, Wv} (blockIdx.y).
// M = B*T = 16384, N = 128, K = 2048. Block tile 128x128x16, 256 threads,
// 8x8 outputs/thread (2x2 quadrants of 4x4).
// ---------------------------------------------------------------------------
__global__ __launch_bounds__(256) void qkv_gemm(
    const float* __restrict__ x,
    const float* __restrict__ Wq,
    const float* __restrict__ Wk,
    const float* __restrict__ Wv)
{
    __shared__ float As[16][132];   // transposed A tile, padded
    __shared__ float Bs[16][128];

    const float* W;
    float* out;
    if (blockIdx.y == 0)      { W = Wq; out = g_Q; }
    else if (blockIdx.y == 1) { W = Wk; out = g_K; }
    else                      { W = Wv; out = g_V; }

    const int tid = threadIdx.x;
    const int tx  = tid & 15;    // n dim
    const int ty  = tid >> 4;    // m dim
    const int m0  = blockIdx.x * 128;

    float acc[8][8];
#pragma unroll
    for (int i = 0; i < 8; i++)
#pragma unroll
        for (int j = 0; j < 8; j++) acc[i][j] = 0.0f;

    for (int k0 = 0; k0 < C_; k0 += 16) {
        // Load A tile (128 rows x 16 k), store transposed As[k][m]
#pragma unroll
        for (int i = 0; i < 2; i++) {
            int idx = tid + i * 256;
            int row = idx >> 2;
            int c4  = (idx & 3) << 2;
            float4 v = *(const float4*)(x + (size_t)(m0 + row) * C_ + k0 + c4);
            As[c4 + 0][row] = v.x;
            As[c4 + 1][row] = v.y;
            As[c4 + 2][row] = v.z;
            As[c4 + 3][row] = v.w;
        }
        // Load B tile (16 k x 128 n)
#pragma unroll
        for (int i = 0; i < 2; i++) {
            int idx = tid + i * 256;
            int row = idx >> 5;
            int n4  = (idx & 31) << 2;
            *(float4*)&Bs[row][n4] = *(const float4*)(W + (size_t)(k0 + row) * HS_ + n4);
        }
        __syncthreads();

#pragma unroll
        for (int k = 0; k < 16; k++) {
            float a[8], b[8];
            *(float4*)&a[0] = *(float4*)&As[k][ty * 4];
            *(float4*)&a[4] = *(float4*)&As[k][64 + ty * 4];
            *(float4*)&b[0] = *(float4*)&Bs[k][tx * 4];
            *(float4*)&b[4] = *(float4*)&Bs[k][64 + tx * 4];
#pragma unroll
            for (int i = 0; i < 8; i++)
#pragma unroll
                for (int j = 0; j < 8; j++)
                    acc[i][j] += a[i] * b[j];
        }
        __syncthreads();
    }

    // Epilogue
#pragma unroll
    for (int i = 0; i < 8; i++) {
        int rloc = (i < 4) ? (ty * 4 + i) : (64 + ty * 4 + (i - 4));
        size_t base = (size_t)(m0 + rloc) * HS_;
        float4 v0 = make_float4(acc[i][0], acc[i][1], acc[i][2], acc[i][3]);
        float4 v1 = make_float4(acc[i][4], acc[i][5], acc[i][6], acc[i][7]);
        *(float4*)(out + base + tx * 4)      = v0;
        *(float4*)(out + base + 64 + tx * 4) = v1;
    }
}

// ---------------------------------------------------------------------------
// Flash attention, fp32, online softmax. BQ = BKT = 64, 256 threads.
// Thread grid 16x16: S tile = 4 rows (ty*4+i) x 4 interleaved cols (tx+16*jj);
// O tile = 4 rows x 8 cols (tx*4+j quadrants).
// Each block processes q-tiles {x, 63-x} for perfect causal load balance.
// ---------------------------------------------------------------------------
#define QSTR 132
#define PSTR 68
#define SMEM_FA ((64 * QSTR + 64 * QSTR + 64 * PSTR) * 4)

__device__ __forceinline__ float rmax16(float v) {
    v = fmaxf(v, __shfl_xor_sync(0xffffffffu, v, 8));
    v = fmaxf(v, __shfl_xor_sync(0xffffffffu, v, 4));
    v = fmaxf(v, __shfl_xor_sync(0xffffffffu, v, 2));
    v = fmaxf(v, __shfl_xor_sync(0xffffffffu, v, 1));
    return v;
}
__device__ __forceinline__ float rsum16(float v) {
    v += __shfl_xor_sync(0xffffffffu, v, 8);
    v += __shfl_xor_sync(0xffffffffu, v, 4);
    v += __shfl_xor_sync(0xffffffffu, v, 2);
    v += __shfl_xor_sync(0xffffffffu, v, 1);
    return v;
}

__global__ __launch_bounds__(256) void flash_attn(float* __restrict__ y)
{
    extern __shared__ float sm[];
    float* Qs  = sm;                  // [64][QSTR]
    float* KVs = sm + 64 * QSTR;      // [64][QSTR] shared by K then V
    float* Ps  = sm + 2 * 64 * QSTR;  // [64][PSTR]

    const int tid = threadIdx.x;
    const int tx  = tid & 15;
    const int ty  = tid >> 4;
    const int b   = blockIdx.y;
    const float SCALE = 0.08838834764831845f;  // 1/sqrt(128)

    for (int half = 0; half < 2; half++) {
        const int qt    = half ? (63 - (int)blockIdx.x) : (int)blockIdx.x;
        const int qbase = qt * 64;
        const float* Qg = g_Q + ((size_t)b * T_ + qbase) * HS_;

        __syncthreads();  // protect smem reuse across halves

        // Load Q tile
#pragma unroll
        for (int i = 0; i < 8; i++) {
            int idx = tid + i * 256;
            int r   = idx >> 5;
            int d4  = (idx & 31) << 2;
            *(float4*)&Qs[r * QSTR + d4] = *(const float4*)(Qg + (size_t)r * HS_ + d4);
        }

        float o[4][8];
        float m_i[4], l_i[4];
#pragma unroll
        for (int i = 0; i < 4; i++) {
            m_i[i] = -1e30f;
            l_i[i] = 0.0f;
#pragma unroll
            for (int j = 0; j < 8; j++) o[i][j] = 0.0f;
        }

        for (int kt = 0; kt <= qt; kt++) {
            const int kbase = kt * 64;
            const float* Kg = g_K + ((size_t)b * T_ + kbase) * HS_;
            const float* Vg = g_V + ((size_t)b * T_ + kbase) * HS_;

            __syncthreads();  // previous PV done reading KVs
            // Load K tile
#pragma unroll
            for (int i = 0; i < 8; i++) {
                int idx = tid + i * 256;
                int r   = idx >> 5;
                int d4  = (idx & 31) << 2;
                *(float4*)&KVs[r * QSTR + d4] = *(const float4*)(Kg + (size_t)r * HS_ + d4);
            }
            __syncthreads();

            // S = Q @ K^T for this tile
            float s[4][4];
#pragma unroll
            for (int i = 0; i < 4; i++)
#pragma unroll
                for (int jj = 0; jj < 4; jj++) s[i][jj] = 0.0f;

            for (int d = 0; d < HS_; d += 4) {
                float4 a4[4], b4[4];
#pragma unroll
                for (int i = 0; i < 4; i++)
                    a4[i] = *(float4*)&Qs[(ty * 4 + i) * QSTR + d];
#pragma unroll
                for (int jj = 0; jj < 4; jj++)
                    b4[jj] = *(float4*)&KVs[(tx + 16 * jj) * QSTR + d];
#pragma unroll
                for (int i = 0; i < 4; i++)
#pragma unroll
                    for (int jj = 0; jj < 4; jj++)
                        s[i][jj] += a4[i].x * b4[jj].x + a4[i].y * b4[jj].y +
                                    a4[i].z * b4[jj].z + a4[i].w * b4[jj].w;
            }

            // Online softmax update
            const bool diag = (kt == qt);
#pragma unroll
            for (int i = 0; i < 4; i++) {
                const int qr = qbase + ty * 4 + i;
                float rm = -1e30f;
#pragma unroll
                for (int jj = 0; jj < 4; jj++) {
                    float v = s[i][jj] * SCALE;
                    if (diag && (kbase + tx + 16 * jj > qr)) v = -1e30f;
                    s[i][jj] = v;
                    rm = fmaxf(rm, v);
                }
                rm = rmax16(rm);
                const float mn  = fmaxf(m_i[i], rm);
                const float fac = __expf(m_i[i] - mn);
                float rs = 0.0f;
#pragma unroll
                for (int jj = 0; jj < 4; jj++) {
                    float p = __expf(s[i][jj] - mn);
                    Ps[(ty * 4 + i) * PSTR + tx + 16 * jj] = p;
                    rs += p;
                }
                rs = rsum16(rs);
                l_i[i] = l_i[i] * fac + rs;
                m_i[i] = mn;
#pragma unroll
                for (int j = 0; j < 8; j++) o[i][j] *= fac;
            }
            __syncthreads();  // Ps written, S done reading KVs

            // Load V tile (reuses KVs)
#pragma unroll
            for (int i = 0; i < 8; i++) {
                int idx = tid + i * 256;
                int r   = idx >> 5;
                int d4  = (idx & 31) << 2;
                *(float4*)&KVs[r * QSTR + d4] = *(const float4*)(Vg + (size_t)r * HS_ + d4);
            }
            __syncthreads();

            // O += P @ V
            for (int k = 0; k < 64; k += 4) {
                float4 p4[4];
#pragma unroll
                for (int i = 0; i < 4; i++)
                    p4[i] = *(float4*)&Ps[(ty * 4 + i) * PSTR + k];
#pragma unroll
                for (int kk = 0; kk < 4; kk++) {
                    float4 va = *(float4*)&KVs[(k + kk) * QSTR + tx * 4];
                    float4 vb = *(float4*)&KVs[(k + kk) * QSTR + 64 + tx * 4];
#pragma unroll
                    for (int i = 0; i < 4; i++) {
                        float p = ((const float*)&p4[i])[kk];
                        o[i][0] += p * va.x; o[i][1] += p * va.y;
                        o[i][2] += p * va.z; o[i][3] += p * va.w;
                        o[i][4] += p * vb.x; o[i][5] += p * vb.y;
                        o[i][6] += p * vb.z; o[i][7] += p * vb.w;
                    }
                }
            }
        }

        // Epilogue: normalize and store
#pragma unroll
        for (int i = 0; i < 4; i++) {
            const float inv = 1.0f / l_i[i];
            const int r = qbase + ty * 4 + i;
            size_t base = ((size_t)b * T_ + r) * HS_;
            float4 v0 = make_float4(o[i][0] * inv, o[i][1] * inv, o[i][2] * inv, o[i][3] * inv);
            float4 v1 = make_float4(o[i][4] * inv, o[i][5] * inv, o[i][6] * inv, o[i][7] * inv);
            *(float4*)(y + base + tx * 4)      = v0;
            *(float4*)(y + base + 64 + tx * 4) = v1;
        }
    }
}

// ---------------------------------------------------------------------------
extern "C" void kernel_launch(void* const* d_in, const int* in_sizes, int n_in,
                              void* d_out, int out_size)
{
    const float* x  = (const float*)d_in[0];
    const float* Wq = (const float*)d_in[1];
    const float* Wk = (const float*)d_in[2];
    const float* Wv = (const float*)d_in[3];
    float* y = (float*)d_out;

    (void)in_sizes; (void)n_in; (void)out_size;

    // QKV projections: M-tiles x {q,k,v}
    qkv_gemm<<<dim3(128, 3), 256>>>(x, Wq, Wk, Wv);

    // Flash attention: 32 balanced q-tile pairs x 4 batches
    cudaFuncSetAttribute(flash_attn, cudaFuncAttributeMaxDynamicSharedMemorySize, SMEM_FA);
    flash_attn<<<dim3(32, 4), 256, SMEM_FA>>>(y);
}

// round 3
// speedup vs baseline: 1.4307x; 1.4307x over previous
#include <cuda_runtime.h>
#include <cuda_bf16.h>
#include <cstdint>
#include <math.h>

#define B_  4
#define T_  4096
#define C_  2048
#define HS_ 128
#define MT  16384   // B_*T_

// Scratch (device globals per harness rules)
__device__ float g_Q[MT * HS_];
__device__ float g_K[MT * HS_];
__device__ float g_V[MT * HS_];
__device__ __align__(16) __nv_bfloat16 g_Wth[3][HS_ * C_];  // W^T hi, [n][k] K-major
__device__ __align__(16) __nv_bfloat16 g_Wtl[3][HS_ * C_];  // W^T lo

// ---------------------------------------------------------------------------
// Helpers: mma.sync bf16 (sm_80+ PTX, works on plain compute_103), ldmatrix,
// cp.async. NO tcgen05 — the harness builds non-'a' PTX.
// ---------------------------------------------------------------------------
__device__ __forceinline__ uint32_t smem_u32(const void* p) {
    uint32_t a;
    asm("{ .reg .u64 t; cvta.to.shared.u64 t, %1; cvt.u32.u64 %0, t; }" : "=r"(a) : "l"(p));
    return a;
}
__device__ __forceinline__ void cp_async16(uint32_t dst, const void* src) {
    asm volatile("cp.async.ca.shared.global [%0], [%1], 16;" :: "r"(dst), "l"(src));
}
__device__ __forceinline__ void ldm_x4(uint32_t* r, uint32_t addr) {
    asm volatile("ldmatrix.sync.aligned.m8n8.x4.shared.b16 {%0,%1,%2,%3}, [%4];"
        : "=r"(r[0]), "=r"(r[1]), "=r"(r[2]), "=r"(r[3]) : "r"(addr));
}
__device__ __forceinline__ void mma_bf16(float* d, const uint32_t* a, uint32_t b0, uint32_t b1) {
    asm volatile("mma.sync.aligned.m16n8k16.row.col.f32.bf16.bf16.f32 "
        "{%0,%1,%2,%3}, {%4,%5,%6,%7}, {%8,%9}, {%0,%1,%2,%3};"
        : "+f"(d[0]), "+f"(d[1]), "+f"(d[2]), "+f"(d[3])
        : "r"(a[0]), "r"(a[1]), "r"(a[2]), "r"(a[3]), "r"(b0), "r"(b1));
}
__device__ __forceinline__ uint32_t pack_bf16(float a, float b) {
    __nv_bfloat162 t = __floats2bfloat162_rn(a, b);
    return *reinterpret_cast<uint32_t*>(&t);
}

// ---------------------------------------------------------------------------
// Prep: W [2048,128] fp32 -> W^T hi/lo bf16 [128,2048] (K-major for MMA B)
// ---------------------------------------------------------------------------
__global__ __launch_bounds__(256) void prep_w(
    const float* __restrict__ Wq, const float* __restrict__ Wk, const float* __restrict__ Wv)
{
    __shared__ float t[32][33];
    const int mi = blockIdx.z;
    const float* W = (mi == 0) ? Wq : ((mi == 1) ? Wk : Wv);
    const int k0 = blockIdx.x * 32, n0 = blockIdx.y * 32;
    const int tx = threadIdx.x & 31, ty = threadIdx.x >> 5;
#pragma unroll
    for (int i = 0; i < 32; i += 8)
        t[ty + i][tx] = W[(size_t)(k0 + ty + i) * HS_ + n0 + tx];
    __syncthreads();
#pragma unroll
    for (int i = 0; i < 32; i += 8) {
        float v = t[tx][ty + i];
        __nv_bfloat16 h = __float2bfloat16(v);
        __nv_bfloat16 l = __float2bfloat16(v - __bfloat162float(h));
        size_t o = (size_t)(n0 + ty + i) * C_ + (k0 + tx);
        g_Wth[mi][o] = h;
        g_Wtl[mi][o] = l;
    }
}

// ---------------------------------------------------------------------------
// QKV projection via mma.sync bf16 split precision (hi*hi + hi*lo + lo*hi).
// CTA 128(m) x 128(n), 8 warps (4m x 2n), warp tile 32x64. K chunks of 64,
// double-buffered smem with padded stride 72 bf16 (144 B) for conflict-free
// ldmatrix. grid (128 m-tiles, 3 matrices).
// ---------------------------------------------------------------------------
#define KC     64
#define NCHUNK (C_ / KC)      // 32
#define ASTRB  144            // bytes per smem row (72 bf16)
#define TILEB  (128 * ASTRB)  // 18432 bytes per (hi|lo) tile
#define STAGEB (4 * TILEB)    // Ahi, Alo, Bhi, Blo
#define SMEM_QKV (2 * STAGEB) // 147456

__global__ __launch_bounds__(256, 1) void qkv_mma(const float* __restrict__ x)
{
    extern __shared__ char smem[];
    const uint32_t sb = smem_u32(smem);
    const int tid  = threadIdx.x;
    const int lane = tid & 31, wid = tid >> 5;
    const int wm = wid >> 1, wn = wid & 1;   // warp grid 4x2
    const int m0 = blockIdx.x * 128;
    const int mi = blockIdx.y;               // matrix: 0 q, 1 k, 2 v

    const __nv_bfloat16* Wh = g_Wth[mi];
    const __nv_bfloat16* Wl = g_Wtl[mi];
    float* out = (mi == 0) ? g_Q : ((mi == 1) ? g_K : g_V);

    float acc[2][8][4];
#pragma unroll
    for (int i = 0; i < 2; i++)
#pragma unroll
        for (int j = 0; j < 8; j++)
#pragma unroll
            for (int k = 0; k < 4; k++) acc[i][j][k] = 0.0f;

    // -------- load helpers (as lambdas over tid) --------
    auto loadB = [&](int s, int c) {
        const uint32_t bh = sb + s * STAGEB + 2 * TILEB;
        const uint32_t bl = bh + TILEB;
#pragma unroll
        for (int t = 0; t < 8; t++) {
            const int idx = tid + t * 256;          // 0..2047
            const int half = idx >> 10;
            const int w = idx & 1023;
            const int n = w >> 3, kk = w & 7;       // row n, 16B chunk kk
            const __nv_bfloat16* base = half ? Wl : Wh;
            const char* src = (const char*)(base + (size_t)n * C_ + c * KC) + kk * 16;
            cp_async16((half ? bl : bh) + (uint32_t)(n * ASTRB + kk * 16), src);
        }
        asm volatile("cp.async.commit_group;");
    };
    auto loadA = [&](float4* ar, int c) {
#pragma unroll
        for (int t = 0; t < 8; t++) {
            const int idx = tid + t * 256;
            const int r = idx >> 4, f = idx & 15;
            ar[t] = *(const float4*)(x + (size_t)(m0 + r) * C_ + c * KC + f * 4);
        }
    };
    auto storeA = [&](int s, const float4* ar) {
        char* ah = smem + s * STAGEB;
        char* al = ah + TILEB;
#pragma unroll
        for (int t = 0; t < 8; t++) {
            const int idx = tid + t * 256;
            const int r = idx >> 4, f = idx & 15;
            float4 v = ar[t];
            __nv_bfloat16 hx = __float2bfloat16(v.x), hy = __float2bfloat16(v.y);
            __nv_bfloat16 hz = __float2bfloat16(v.z), hw = __float2bfloat16(v.w);
            uint2 hp, lp;
            hp.x = pack_bf16(__bfloat162float(hx), __bfloat162float(hy));
            hp.y = pack_bf16(__bfloat162float(hz), __bfloat162float(hw));
            lp.x = pack_bf16(v.x - __bfloat162float(hx), v.y - __bfloat162float(hy));
            lp.y = pack_bf16(v.z - __bfloat162float(hz), v.w - __bfloat162float(hw));
            const uint32_t o = (uint32_t)(r * ASTRB + f * 8);
            *(uint2*)(ah + o) = hp;
            *(uint2*)(al + o) = lp;
        }
    };

    // ldmatrix per-lane base offsets (within a tile)
    const uint32_t aRowOff = (uint32_t)((wm * 32 + (lane & 15)) * ASTRB + (lane >> 4) * 16);
    const uint32_t bRowOff = (uint32_t)((wn * 64 + (lane & 15)) * ASTRB + (lane >> 4) * 16);

    // -------- prologue: chunk 0 --------
    float4 areg[8];
    loadB(0, 0);
    loadA(areg, 0);
    storeA(0, areg);
    asm volatile("cp.async.wait_group 0;" ::: "memory");
    __syncthreads();

    for (int c = 0; c < NCHUNK; c++) {
        const int s = c & 1;
        if (c + 1 < NCHUNK) {
            loadB(s ^ 1, c + 1);
            loadA(areg, c + 1);
        }

        const uint32_t ah = sb + s * STAGEB;
        const uint32_t al = ah + TILEB;
        const uint32_t bh = ah + 2 * TILEB;
        const uint32_t bl = ah + 3 * TILEB;

#pragma unroll
        for (int ks = 0; ks < 4; ks++) {
            uint32_t aF[2][4], aL[2][4], bF[4][4], bL[4][4];
#pragma unroll
            for (int mt = 0; mt < 2; mt++) {
                const uint32_t off = aRowOff + (uint32_t)(mt * 16 * ASTRB + ks * 32);
                ldm_x4(aF[mt], ah + off);
                ldm_x4(aL[mt], al + off);
            }
#pragma unroll
            for (int nt = 0; nt < 4; nt++) {
                const uint32_t off = bRowOff + (uint32_t)(nt * 16 * ASTRB + ks * 32);
                ldm_x4(bF[nt], bh + off);
                ldm_x4(bL[nt], bl + off);
            }
#pragma unroll
            for (int mt = 0; mt < 2; mt++) {
#pragma unroll
                for (int nt = 0; nt < 4; nt++) {
                    float* d0 = acc[mt][nt * 2];
                    float* d1 = acc[mt][nt * 2 + 1];
                    mma_bf16(d0, aF[mt], bF[nt][0], bF[nt][2]);   // hi*hi
                    mma_bf16(d1, aF[mt], bF[nt][1], bF[nt][3]);
                    mma_bf16(d0, aF[mt], bL[nt][0], bL[nt][2]);   // hi*lo
                    mma_bf16(d1, aF[mt], bL[nt][1], bL[nt][3]);
                    mma_bf16(d0, aL[mt], bF[nt][0], bF[nt][2]);   // lo*hi
                    mma_bf16(d1, aL[mt], bF[nt][1], bF[nt][3]);
                }
            }
        }

        if (c + 1 < NCHUNK) {
            storeA(s ^ 1, areg);
            asm volatile("cp.async.wait_group 0;" ::: "memory");
        }
        __syncthreads();
    }

    // -------- epilogue: accumulators -> fp32 output --------
    const int g = lane >> 2, tg = lane & 3;
#pragma unroll
    for (int mt = 0; mt < 2; mt++) {
#pragma unroll
        for (int nf = 0; nf < 8; nf++) {
            const int n0 = wn * 64 + (nf >> 1) * 16 + (nf & 1) * 8 + tg * 2;
            const int r0 = m0 + wm * 32 + mt * 16 + g;
            float* d = acc[mt][nf];
            *(float2*)(out + (size_t)r0 * HS_ + n0)       = make_float2(d[0], d[1]);
            *(float2*)(out + (size_t)(r0 + 8) * HS_ + n0) = make_float2(d[2], d[3]);
        }
    }
}

// ---------------------------------------------------------------------------
// Flash attention, fp32, online softmax (unchanged). BQ = BKT = 64.
// ---------------------------------------------------------------------------
#define QSTR 132
#define PSTR 68
#define SMEM_FA ((64 * QSTR + 64 * QSTR + 64 * PSTR) * 4)

__device__ __forceinline__ float rmax16(float v) {
    v = fmaxf(v, __shfl_xor_sync(0xffffffffu, v, 8));
    v = fmaxf(v, __shfl_xor_sync(0xffffffffu, v, 4));
    v = fmaxf(v, __shfl_xor_sync(0xffffffffu, v, 2));
    v = fmaxf(v, __shfl_xor_sync(0xffffffffu, v, 1));
    return v;
}
__device__ __forceinline__ float rsum16(float v) {
    v += __shfl_xor_sync(0xffffffffu, v, 8);
    v += __shfl_xor_sync(0xffffffffu, v, 4);
    v += __shfl_xor_sync(0xffffffffu, v, 2);
    v += __shfl_xor_sync(0xffffffffu, v, 1);
    return v;
}

__global__ __launch_bounds__(256) void flash_attn(float* __restrict__ y)
{
    extern __shared__ float sm[];
    float* Qs  = sm;
    float* KVs = sm + 64 * QSTR;
    float* Ps  = sm + 2 * 64 * QSTR;

    const int tid = threadIdx.x;
    const int tx  = tid & 15;
    const int ty  = tid >> 4;
    const int b   = blockIdx.y;
    const float SCALE = 0.08838834764831845f;

    for (int half = 0; half < 2; half++) {
        const int qt    = half ? (63 - (int)blockIdx.x) : (int)blockIdx.x;
        const int qbase = qt * 64;
        const float* Qg = g_Q + ((size_t)b * T_ + qbase) * HS_;

        __syncthreads();

#pragma unroll
        for (int i = 0; i < 8; i++) {
            int idx = tid + i * 256;
            int r   = idx >> 5;
            int d4  = (idx & 31) << 2;
            *(float4*)&Qs[r * QSTR + d4] = *(const float4*)(Qg + (size_t)r * HS_ + d4);
        }

        float o[4][8];
        float m_i[4], l_i[4];
#pragma unroll
        for (int i = 0; i < 4; i++) {
            m_i[i] = -1e30f; l_i[i] = 0.0f;
#pragma unroll
            for (int j = 0; j < 8; j++) o[i][j] = 0.0f;
        }

        for (int kt = 0; kt <= qt; kt++) {
            const int kbase = kt * 64;
            const float* Kg = g_K + ((size_t)b * T_ + kbase) * HS_;
            const float* Vg = g_V + ((size_t)b * T_ + kbase) * HS_;

            __syncthreads();
#pragma unroll
            for (int i = 0; i < 8; i++) {
                int idx = tid + i * 256;
                int r   = idx >> 5;
                int d4  = (idx & 31) << 2;
                *(float4*)&KVs[r * QSTR + d4] = *(const float4*)(Kg + (size_t)r * HS_ + d4);
            }
            __syncthreads();

            float s[4][4];
#pragma unroll
            for (int i = 0; i < 4; i++)
#pragma unroll
                for (int jj = 0; jj < 4; jj++) s[i][jj] = 0.0f;

            for (int d = 0; d < HS_; d += 4) {
                float4 a4[4], b4[4];
#pragma unroll
                for (int i = 0; i < 4; i++)
                    a4[i] = *(float4*)&Qs[(ty * 4 + i) * QSTR + d];
#pragma unroll
                for (int jj = 0; jj < 4; jj++)
                    b4[jj] = *(float4*)&KVs[(tx + 16 * jj) * QSTR + d];
#pragma unroll
                for (int i = 0; i < 4; i++)
#pragma unroll
                    for (int jj = 0; jj < 4; jj++)
                        s[i][jj] += a4[i].x * b4[jj].x + a4[i].y * b4[jj].y +
                                    a4[i].z * b4[jj].z + a4[i].w * b4[jj].w;
            }

            const bool diag = (kt == qt);
#pragma unroll
            for (int i = 0; i < 4; i++) {
                const int qr = qbase + ty * 4 + i;
                float rm = -1e30f;
#pragma unroll
                for (int jj = 0; jj < 4; jj++) {
                    float v = s[i][jj] * SCALE;
                    if (diag && (kbase + tx + 16 * jj > qr)) v = -1e30f;
                    s[i][jj] = v;
                    rm = fmaxf(rm, v);
                }
                rm = rmax16(rm);
                const float mn  = fmaxf(m_i[i], rm);
                const float fac = __expf(m_i[i] - mn);
                float rs = 0.0f;
#pragma unroll
                for (int jj = 0; jj < 4; jj++) {
                    float p = __expf(s[i][jj] - mn);
                    Ps[(ty * 4 + i) * PSTR + tx + 16 * jj] = p;
                    rs += p;
                }
                rs = rsum16(rs);
                l_i[i] = l_i[i] * fac + rs;
                m_i[i] = mn;
#pragma unroll
                for (int j = 0; j < 8; j++) o[i][j] *= fac;
            }
            __syncthreads();

#pragma unroll
            for (int i = 0; i < 8; i++) {
                int idx = tid + i * 256;
                int r   = idx >> 5;
                int d4  = (idx & 31) << 2;
                *(float4*)&KVs[r * QSTR + d4] = *(const float4*)(Vg + (size_t)r * HS_ + d4);
            }
            __syncthreads();

            for (int k = 0; k < 64; k += 4) {
                float4 p4[4];
#pragma unroll
                for (int i = 0; i < 4; i++)
                    p4[i] = *(float4*)&Ps[(ty * 4 + i) * PSTR + k];
#pragma unroll
                for (int kk = 0; kk < 4; kk++) {
                    float4 va = *(float4*)&KVs[(k + kk) * QSTR + tx * 4];
                    float4 vb = *(float4*)&KVs[(k + kk) * QSTR + 64 + tx * 4];
#pragma unroll
                    for (int i = 0; i < 4; i++) {
                        float p = ((const float*)&p4[i])[kk];
                        o[i][0] += p * va.x; o[i][1] += p * va.y;
                        o[i][2] += p * va.z; o[i][3] += p * va.w;
                        o[i][4] += p * vb.x; o[i][5] += p * vb.y;
                        o[i][6] += p * vb.z; o[i][7] += p * vb.w;
                    }
                }
            }
        }

#pragma unroll
        for (int i = 0; i < 4; i++) {
            const float inv = 1.0f / l_i[i];
            const int r = qbase + ty * 4 + i;
            size_t base = ((size_t)b * T_ + r) * HS_;
            float4 v0 = make_float4(o[i][0] * inv, o[i][1] * inv, o[i][2] * inv, o[i][3] * inv);
            float4 v1 = make_float4(o[i][4] * inv, o[i][5] * inv, o[i][6] * inv, o[i][7] * inv);
            *(float4*)(y + base + tx * 4)      = v0;
            *(float4*)(y + base + 64 + tx * 4) = v1;
        }
    }
}

// ---------------------------------------------------------------------------
extern "C" void kernel_launch(void* const* d_in, const int* in_sizes, int n_in,
                              void* d_out, int out_size)
{
    const float* x  = (const float*)d_in[0];
    const float* Wq = (const float*)d_in[1];
    const float* Wk = (const float*)d_in[2];
    const float* Wv = (const float*)d_in[3];
    float* y = (float*)d_out;
    (void)in_sizes; (void)n_in; (void)out_size;

    prep_w<<<dim3(64, 4, 3), 256>>>(Wq, Wk, Wv);

    cudaFuncSetAttribute(qkv_mma, cudaFuncAttributeMaxDynamicSharedMemorySize, SMEM_QKV);
    qkv_mma<<<dim3(128, 3), 256, SMEM_QKV>>>(x);

    cudaFuncSetAttribute(flash_attn, cudaFuncAttributeMaxDynamicSharedMemorySize, SMEM_FA);
    flash_attn<<<dim3(32, 4), 256, SMEM_FA>>>(y);
}

// round 4
// speedup vs baseline: 2.1479x; 1.5013x over previous
#include <cuda_runtime.h>
#include <cuda_bf16.h>
#include <cstdint>
#include <math.h>

#define B_  4
#define T_  4096
#define C_  2048
#define HS_ 128
#define MT  16384   // B_*T_

// Scratch (device globals per harness rules): Q/K/V as split bf16 hi/lo
__device__ __align__(16) __nv_bfloat16 g_Qh[MT * HS_];
__device__ __align__(16) __nv_bfloat16 g_Ql[MT * HS_];
__device__ __align__(16) __nv_bfloat16 g_Kh[MT * HS_];
__device__ __align__(16) __nv_bfloat16 g_Kl[MT * HS_];
__device__ __align__(16) __nv_bfloat16 g_Vh[MT * HS_];
__device__ __align__(16) __nv_bfloat16 g_Vl[MT * HS_];
__device__ __align__(16) __nv_bfloat16 g_Wth[3][HS_ * C_];  // W^T hi, [n][k]
__device__ __align__(16) __nv_bfloat16 g_Wtl[3][HS_ * C_];  // W^T lo

// ---------------------------------------------------------------------------
// Helpers: mma.sync bf16 / ldmatrix / cp.async (baseline PTX, no tcgen05)
// ---------------------------------------------------------------------------
__device__ __forceinline__ uint32_t smem_u32(const void* p) {
    uint32_t a;
    asm("{ .reg .u64 t; cvta.to.shared.u64 t, %1; cvt.u32.u64 %0, t; }" : "=r"(a) : "l"(p));
    return a;
}
__device__ __forceinline__ void cp_async16(uint32_t dst, const void* src) {
    asm volatile("cp.async.ca.shared.global [%0], [%1], 16;" :: "r"(dst), "l"(src));
}
__device__ __forceinline__ void ldm_x4(uint32_t* r, uint32_t addr) {
    asm volatile("ldmatrix.sync.aligned.m8n8.x4.shared.b16 {%0,%1,%2,%3}, [%4];"
        : "=r"(r[0]), "=r"(r[1]), "=r"(r[2]), "=r"(r[3]) : "r"(addr));
}
__device__ __forceinline__ void ldm_x4_t(uint32_t* r, uint32_t addr) {
    asm volatile("ldmatrix.sync.aligned.m8n8.x4.trans.shared.b16 {%0,%1,%2,%3}, [%4];"
        : "=r"(r[0]), "=r"(r[1]), "=r"(r[2]), "=r"(r[3]) : "r"(addr));
}
__device__ __forceinline__ void mma_bf16(float* d, const uint32_t* a, uint32_t b0, uint32_t b1) {
    asm volatile("mma.sync.aligned.m16n8k16.row.col.f32.bf16.bf16.f32 "
        "{%0,%1,%2,%3}, {%4,%5,%6,%7}, {%8,%9}, {%0,%1,%2,%3};"
        : "+f"(d[0]), "+f"(d[1]), "+f"(d[2]), "+f"(d[3])
        : "r"(a[0]), "r"(a[1]), "r"(a[2]), "r"(a[3]), "r"(b0), "r"(b1));
}
__device__ __forceinline__ uint32_t pack_bf16(float a, float b) {
    __nv_bfloat162 t = __floats2bfloat162_rn(a, b);
    return *reinterpret_cast<uint32_t*>(&t);
}
__device__ __forceinline__ float bf16v(float x) {     // value of round-to-bf16
    return __bfloat162float(__float2bfloat16(x));
}

// ---------------------------------------------------------------------------
// Prep: W [2048,128] fp32 -> W^T hi/lo bf16 [128,2048] (K-major for MMA B)
// ---------------------------------------------------------------------------
__global__ __launch_bounds__(256) void prep_w(
    const float* __restrict__ Wq, const float* __restrict__ Wk, const float* __restrict__ Wv)
{
    __shared__ float t[32][33];
    const int mi = blockIdx.z;
    const float* W = (mi == 0) ? Wq : ((mi == 1) ? Wk : Wv);
    const int k0 = blockIdx.x * 32, n0 = blockIdx.y * 32;
    const int tx = threadIdx.x & 31, ty = threadIdx.x >> 5;
#pragma unroll
    for (int i = 0; i < 32; i += 8)
        t[ty + i][tx] = W[(size_t)(k0 + ty + i) * HS_ + n0 + tx];
    __syncthreads();
#pragma unroll
    for (int i = 0; i < 32; i += 8) {
        float v = t[tx][ty + i];
        __nv_bfloat16 h = __float2bfloat16(v);
        __nv_bfloat16 l = __float2bfloat16(v - __bfloat162float(h));
        size_t o = (size_t)(n0 + ty + i) * C_ + (k0 + tx);
        g_Wth[mi][o] = h;
        g_Wtl[mi][o] = l;
    }
}

// ---------------------------------------------------------------------------
// QKV projection via mma.sync split-bf16. Epilogue writes bf16 hi/lo.
// CTA 128x128, 8 warps (4m x 2n), warp tile 32x64, K chunks 64, double buffer.
// ---------------------------------------------------------------------------
#define KC     64
#define NCHUNK (C_ / KC)      // 32
#define ASTRB  144            // bytes per smem row (72 bf16)
#define TILEB  (128 * ASTRB)
#define STAGEB (4 * TILEB)
#define SMEM_QKV (2 * STAGEB) // 147456

__global__ __launch_bounds__(256, 1) void qkv_mma(const float* __restrict__ x)
{
    extern __shared__ char smem[];
    const uint32_t sb = smem_u32(smem);
    const int tid  = threadIdx.x;
    const int lane = tid & 31, wid = tid >> 5;
    const int wm = wid >> 1, wn = wid & 1;
    const int m0 = blockIdx.x * 128;
    const int mi = blockIdx.y;

    const __nv_bfloat16* Wh = g_Wth[mi];
    const __nv_bfloat16* Wl = g_Wtl[mi];
    __nv_bfloat16* oh = (mi == 0) ? g_Qh : ((mi == 1) ? g_Kh : g_Vh);
    __nv_bfloat16* ol = (mi == 0) ? g_Ql : ((mi == 1) ? g_Kl : g_Vl);

    float acc[2][8][4];
#pragma unroll
    for (int i = 0; i < 2; i++)
#pragma unroll
        for (int j = 0; j < 8; j++)
#pragma unroll
            for (int k = 0; k < 4; k++) acc[i][j][k] = 0.0f;

    auto loadB = [&](int s, int c) {
        const uint32_t bh = sb + s * STAGEB + 2 * TILEB;
        const uint32_t bl = bh + TILEB;
#pragma unroll
        for (int t = 0; t < 8; t++) {
            const int idx = tid + t * 256;
            const int half = idx >> 10;
            const int w = idx & 1023;
            const int n = w >> 3, kk = w & 7;
            const __nv_bfloat16* base = half ? Wl : Wh;
            const char* src = (const char*)(base + (size_t)n * C_ + c * KC) + kk * 16;
            cp_async16((half ? bl : bh) + (uint32_t)(n * ASTRB + kk * 16), src);
        }
        asm volatile("cp.async.commit_group;");
    };
    auto loadA = [&](float4* ar, int c) {
#pragma unroll
        for (int t = 0; t < 8; t++) {
            const int idx = tid + t * 256;
            const int r = idx >> 4, f = idx & 15;
            ar[t] = *(const float4*)(x + (size_t)(m0 + r) * C_ + c * KC + f * 4);
        }
    };
    auto storeA = [&](int s, const float4* ar) {
        char* ah = smem + s * STAGEB;
        char* al = ah + TILEB;
#pragma unroll
        for (int t = 0; t < 8; t++) {
            const int idx = tid + t * 256;
            const int r = idx >> 4, f = idx & 15;
            float4 v = ar[t];
            __nv_bfloat16 hx = __float2bfloat16(v.x), hy = __float2bfloat16(v.y);
            __nv_bfloat16 hz = __float2bfloat16(v.z), hw = __float2bfloat16(v.w);
            uint2 hp, lp;
            hp.x = pack_bf16(__bfloat162float(hx), __bfloat162float(hy));
            hp.y = pack_bf16(__bfloat162float(hz), __bfloat162float(hw));
            lp.x = pack_bf16(v.x - __bfloat162float(hx), v.y - __bfloat162float(hy));
            lp.y = pack_bf16(v.z - __bfloat162float(hz), v.w - __bfloat162float(hw));
            const uint32_t o = (uint32_t)(r * ASTRB + f * 8);
            *(uint2*)(ah + o) = hp;
            *(uint2*)(al + o) = lp;
        }
    };

    const uint32_t aRowOff = (uint32_t)((wm * 32 + (lane & 15)) * ASTRB + (lane >> 4) * 16);
    const uint32_t bRowOff = (uint32_t)((wn * 64 + (lane & 15)) * ASTRB + (lane >> 4) * 16);

    float4 areg[8];
    loadB(0, 0);
    loadA(areg, 0);
    storeA(0, areg);
    asm volatile("cp.async.wait_group 0;" ::: "memory");
    __syncthreads();

    for (int c = 0; c < NCHUNK; c++) {
        const int s = c & 1;
        if (c + 1 < NCHUNK) {
            loadB(s ^ 1, c + 1);
            loadA(areg, c + 1);
        }
        const uint32_t ah = sb + s * STAGEB;
        const uint32_t al = ah + TILEB;
        const uint32_t bh = ah + 2 * TILEB;
        const uint32_t bl = ah + 3 * TILEB;

#pragma unroll
        for (int ks = 0; ks < 4; ks++) {
            uint32_t aF[2][4], aL[2][4], bF[4][4], bL[4][4];
#pragma unroll
            for (int mt = 0; mt < 2; mt++) {
                const uint32_t off = aRowOff + (uint32_t)(mt * 16 * ASTRB + ks * 32);
                ldm_x4(aF[mt], ah + off);
                ldm_x4(aL[mt], al + off);
            }
#pragma unroll
            for (int nt = 0; nt < 4; nt++) {
                const uint32_t off = bRowOff + (uint32_t)(nt * 16 * ASTRB + ks * 32);
                ldm_x4(bF[nt], bh + off);
                ldm_x4(bL[nt], bl + off);
            }
#pragma unroll
            for (int mt = 0; mt < 2; mt++) {
#pragma unroll
                for (int nt = 0; nt < 4; nt++) {
                    float* d0 = acc[mt][nt * 2];
                    float* d1 = acc[mt][nt * 2 + 1];
                    mma_bf16(d0, aF[mt], bF[nt][0], bF[nt][2]);
                    mma_bf16(d1, aF[mt], bF[nt][1], bF[nt][3]);
                    mma_bf16(d0, aF[mt], bL[nt][0], bL[nt][2]);
                    mma_bf16(d1, aF[mt], bL[nt][1], bL[nt][3]);
                    mma_bf16(d0, aL[mt], bF[nt][0], bF[nt][2]);
                    mma_bf16(d1, aL[mt], bF[nt][1], bF[nt][3]);
                }
            }
        }

        if (c + 1 < NCHUNK) {
            storeA(s ^ 1, areg);
            asm volatile("cp.async.wait_group 0;" ::: "memory");
        }
        __syncthreads();
    }

    // Epilogue: fp32 acc -> bf16 hi/lo
    const int g = lane >> 2, tg = lane & 3;
#pragma unroll
    for (int mt = 0; mt < 2; mt++) {
#pragma unroll
        for (int nf = 0; nf < 8; nf++) {
            const int n0 = wn * 64 + (nf >> 1) * 16 + (nf & 1) * 8 + tg * 2;
            const int r0 = m0 + wm * 32 + mt * 16 + g;
            float* d = acc[mt][nf];
            float h0 = bf16v(d[0]), h1 = bf16v(d[1]);
            float h2 = bf16v(d[2]), h3 = bf16v(d[3]);
            *(uint32_t*)(oh + (size_t)r0 * HS_ + n0)       = pack_bf16(h0, h1);
            *(uint32_t*)(ol + (size_t)r0 * HS_ + n0)       = pack_bf16(d[0] - h0, d[1] - h1);
            *(uint32_t*)(oh + (size_t)(r0 + 8) * HS_ + n0) = pack_bf16(h2, h3);
            *(uint32_t*)(ol + (size_t)(r0 + 8) * HS_ + n0) = pack_bf16(d[2] - h2, d[3] - h3);
        }
    }
}

// ---------------------------------------------------------------------------
// Flash attention via mma.sync, split-bf16 for S and PV, fp32 softmax.
// CTA: 128 q rows, 8 warps x 16 q rows. BK=128 per iteration.
// smem: Qh Ql Kh Kl Vh Vl tiles, 272B row stride (conflict-free ldmatrix).
// ---------------------------------------------------------------------------
#define BQ   128
#define BK   128
#define RSTR 272
#define FTILE (128 * RSTR)          // 34816
#define SMEM_FL (6 * FTILE)         // 208896

__global__ __launch_bounds__(256, 1) void flash_mma(float* __restrict__ y)
{
    extern __shared__ char fsm[];
    const uint32_t sb = smem_u32(fsm);
    const uint32_t Qh = sb,             Ql = sb + FTILE;
    const uint32_t Kh = sb + 2 * FTILE, Kl = sb + 3 * FTILE;
    const uint32_t Vh = sb + 4 * FTILE, Vl = sb + 5 * FTILE;

    const int tid = threadIdx.x, lane = tid & 31, wid = tid >> 5;
    const int qt = blockIdx.x, b = blockIdx.y;
    const int qbase = qt * BQ;
    const float SCALE = 0.08838834764831845f;

    auto load_tile = [&](uint32_t dst, const __nv_bfloat16* src) {
#pragma unroll
        for (int t = 0; t < 8; t++) {
            const int idx = tid + t * 256;
            const int r = idx >> 4, c = idx & 15;
            cp_async16(dst + (uint32_t)(r * RSTR + c * 16), (const char*)src + r * 256 + c * 16);
        }
    };

    const size_t qoff = ((size_t)b * T_ + qbase) * HS_;
    load_tile(Qh, g_Qh + qoff);
    load_tile(Ql, g_Ql + qoff);
    asm volatile("cp.async.commit_group;");
    {
        const size_t koff = ((size_t)b * T_) * HS_;
        load_tile(Kh, g_Kh + koff);
        load_tile(Kl, g_Kl + koff);
        asm volatile("cp.async.commit_group;");
        load_tile(Vh, g_Vh + koff);
        load_tile(Vl, g_Vl + koff);
        asm volatile("cp.async.commit_group;");
    }

    const int g = lane >> 2, tg = lane & 3;
    const uint32_t laneA = (uint32_t)((lane & 15) * RSTR + (lane >> 4) * 16);
    const int rloc0 = wid * 16 + g;          // local q row (and +8)

    float oacc[16][4];
#pragma unroll
    for (int i = 0; i < 16; i++)
#pragma unroll
        for (int j = 0; j < 4; j++) oacc[i][j] = 0.0f;
    float m0_ = -1e30f, m1_ = -1e30f, l0_ = 0.0f, l1_ = 0.0f;

    for (int kt = 0; kt <= qt; kt++) {
        asm volatile("cp.async.wait_group 1;" ::: "memory");  // K(kt) (and Q on kt=0)
        __syncthreads();

        // ---- S = Q K^T (split bf16, 3 passes) ----
        float sacc[16][4];
#pragma unroll
        for (int i = 0; i < 16; i++)
#pragma unroll
            for (int j = 0; j < 4; j++) sacc[i][j] = 0.0f;

#pragma unroll
        for (int ks = 0; ks < 8; ks++) {
            uint32_t aH[4], aL[4];
            const uint32_t aoff = (uint32_t)(wid * 16 * RSTR) + laneA + ks * 32;
            ldm_x4(aH, Qh + aoff);
            ldm_x4(aL, Ql + aoff);
#pragma unroll
            for (int nt2 = 0; nt2 < 8; nt2++) {
                uint32_t kH[4], kL[4];
                const uint32_t koff2 = (uint32_t)(nt2 * 16 * RSTR) + laneA + ks * 32;
                ldm_x4(kH, Kh + koff2);
                ldm_x4(kL, Kl + koff2);
                float* d0 = sacc[nt2 * 2];
                float* d1 = sacc[nt2 * 2 + 1];
                mma_bf16(d0, aH, kH[0], kH[2]);
                mma_bf16(d1, aH, kH[1], kH[3]);
                mma_bf16(d0, aH, kL[0], kL[2]);
                mma_bf16(d1, aH, kL[1], kL[3]);
                mma_bf16(d0, aL, kH[0], kH[2]);
                mma_bf16(d1, aL, kH[1], kH[3]);
            }
        }
        __syncthreads();   // done reading K

        // prefetch next K (clamped; redundant reload on last iter is harmless)
        {
            const int kn = (kt + 1 <= qt) ? (kt + 1) : qt;
            const size_t koff = ((size_t)b * T_ + kn * BK) * HS_;
            load_tile(Kh, g_Kh + koff);
            load_tile(Kl, g_Kl + koff);
            asm volatile("cp.async.commit_group;");
        }
        asm volatile("cp.async.wait_group 1;" ::: "memory");  // V(kt)
        __syncthreads();

        // ---- online softmax (rows rloc0, rloc0+8) ----
        const bool diag = (kt == qt);
        float mx0 = -1e30f, mx1 = -1e30f;
#pragma unroll
        for (int nt = 0; nt < 16; nt++) {
            const int c0 = nt * 8 + tg * 2;
#pragma unroll
            for (int j = 0; j < 2; j++) {
                float v0 = sacc[nt][j] * SCALE;
                float v1 = sacc[nt][2 + j] * SCALE;
                if (diag && (c0 + j > rloc0))     v0 = -1e30f;
                if (diag && (c0 + j > rloc0 + 8)) v1 = -1e30f;
                sacc[nt][j]     = v0;
                sacc[nt][2 + j] = v1;
                mx0 = fmaxf(mx0, v0);
                mx1 = fmaxf(mx1, v1);
            }
        }
        mx0 = fmaxf(mx0, __shfl_xor_sync(0xffffffffu, mx0, 1));
        mx0 = fmaxf(mx0, __shfl_xor_sync(0xffffffffu, mx0, 2));
        mx1 = fmaxf(mx1, __shfl_xor_sync(0xffffffffu, mx1, 1));
        mx1 = fmaxf(mx1, __shfl_xor_sync(0xffffffffu, mx1, 2));

        const float mn0 = fmaxf(m0_, mx0), mn1 = fmaxf(m1_, mx1);
        const float fac0 = __expf(m0_ - mn0), fac1 = __expf(m1_ - mn1);
        m0_ = mn0; m1_ = mn1;

        float rs0 = 0.0f, rs1 = 0.0f;
#pragma unroll
        for (int nt = 0; nt < 16; nt++) {
            float p0 = __expf(sacc[nt][0] - mn0);
            float p1 = __expf(sacc[nt][1] - mn0);
            float p2 = __expf(sacc[nt][2] - mn1);
            float p3 = __expf(sacc[nt][3] - mn1);
            sacc[nt][0] = p0; sacc[nt][1] = p1; sacc[nt][2] = p2; sacc[nt][3] = p3;
            rs0 += p0 + p1; rs1 += p2 + p3;
        }
        rs0 += __shfl_xor_sync(0xffffffffu, rs0, 1);
        rs0 += __shfl_xor_sync(0xffffffffu, rs0, 2);
        rs1 += __shfl_xor_sync(0xffffffffu, rs1, 1);
        rs1 += __shfl_xor_sync(0xffffffffu, rs1, 2);
        l0_ = l0_ * fac0 + rs0;
        l1_ = l1_ * fac1 + rs1;
#pragma unroll
        for (int dt = 0; dt < 16; dt++) {
            oacc[dt][0] *= fac0; oacc[dt][1] *= fac0;
            oacc[dt][2] *= fac1; oacc[dt][3] *= fac1;
        }

        // ---- O += P V (split bf16, 3 passes; P packed from sacc) ----
#pragma unroll
        for (int ks = 0; ks < 8; ks++) {
            float* s0 = sacc[ks * 2];
            float* s1 = sacc[ks * 2 + 1];
            const float h00 = bf16v(s0[0]), h01 = bf16v(s0[1]), h02 = bf16v(s0[2]), h03 = bf16v(s0[3]);
            const float h10 = bf16v(s1[0]), h11 = bf16v(s1[1]), h12 = bf16v(s1[2]), h13 = bf16v(s1[3]);
            uint32_t pah[4], pal[4];
            pah[0] = pack_bf16(h00, h01);
            pah[1] = pack_bf16(h02, h03);
            pah[2] = pack_bf16(h10, h11);
            pah[3] = pack_bf16(h12, h13);
            pal[0] = pack_bf16(s0[0] - h00, s0[1] - h01);
            pal[1] = pack_bf16(s0[2] - h02, s0[3] - h03);
            pal[2] = pack_bf16(s1[0] - h10, s1[1] - h11);
            pal[3] = pack_bf16(s1[2] - h12, s1[3] - h13);
#pragma unroll
            for (int dt2 = 0; dt2 < 8; dt2++) {
                uint32_t vH[4], vL[4];
                const uint32_t voff = (uint32_t)(ks * 16 * RSTR) + laneA + dt2 * 32;
                ldm_x4_t(vH, Vh + voff);
                ldm_x4_t(vL, Vl + voff);
                float* d0 = oacc[dt2 * 2];
                float* d1 = oacc[dt2 * 2 + 1];
                mma_bf16(d0, pah, vH[0], vH[1]);
                mma_bf16(d1, pah, vH[2], vH[3]);
                mma_bf16(d0, pah, vL[0], vL[1]);
                mma_bf16(d1, pah, vL[2], vL[3]);
                mma_bf16(d0, pal, vH[0], vH[1]);
                mma_bf16(d1, pal, vH[2], vH[3]);
            }
        }
        __syncthreads();   // done reading V

        // prefetch next V (clamped)
        {
            const int kn = (kt + 1 <= qt) ? (kt + 1) : qt;
            const size_t koff = ((size_t)b * T_ + kn * BK) * HS_;
            load_tile(Vh, g_Vh + koff);
            load_tile(Vl, g_Vl + koff);
            asm volatile("cp.async.commit_group;");
        }
    }

    asm volatile("cp.async.wait_group 0;" ::: "memory");

    // ---- epilogue: normalize, store fp32 ----
    const float inv0 = 1.0f / l0_, inv1 = 1.0f / l1_;
    const int grow = qbase + rloc0;
    float* y0 = y + ((size_t)b * T_ + grow) * HS_;
    float* y1 = y0 + 8 * HS_;
#pragma unroll
    for (int dt = 0; dt < 16; dt++) {
        const int c = dt * 8 + tg * 2;
        *(float2*)(y0 + c) = make_float2(oacc[dt][0] * inv0, oacc[dt][1] * inv0);
        *(float2*)(y1 + c) = make_float2(oacc[dt][2] * inv1, oacc[dt][3] * inv1);
    }
}

// ---------------------------------------------------------------------------
extern "C" void kernel_launch(void* const* d_in, const int* in_sizes, int n_in,
                              void* d_out, int out_size)
{
    const float* x  = (const float*)d_in[0];
    const float* Wq = (const float*)d_in[1];
    const float* Wk = (const float*)d_in[2];
    const float* Wv = (const float*)d_in[3];
    float* y = (float*)d_out;
    (void)in_sizes; (void)n_in; (void)out_size;

    prep_w<<<dim3(64, 4, 3), 256>>>(Wq, Wk, Wv);

    cudaFuncSetAttribute(qkv_mma, cudaFuncAttributeMaxDynamicSharedMemorySize, SMEM_QKV);
    qkv_mma<<<dim3(128, 3), 256, SMEM_QKV>>>(x);

    cudaFuncSetAttribute(flash_mma, cudaFuncAttributeMaxDynamicSharedMemorySize, SMEM_FL);
    flash_mma<<<dim3(32, 4), 256, SMEM_FL>>>(y);
}

// round 5
// speedup vs baseline: 2.7691x; 1.2892x over previous
#include <cuda_runtime.h>
#include <cuda_bf16.h>
#include <cstdint>
#include <math.h>

#define B_  4
#define T_  4096
#define C_  2048
#define HS_ 128
#define MT  16384   // B_*T_

// Scratch (device globals per harness rules): Q/K/V as split bf16 hi/lo
__device__ __align__(16) __nv_bfloat16 g_Qh[MT * HS_];
__device__ __align__(16) __nv_bfloat16 g_Ql[MT * HS_];
__device__ __align__(16) __nv_bfloat16 g_Kh[MT * HS_];
__device__ __align__(16) __nv_bfloat16 g_Kl[MT * HS_];
__device__ __align__(16) __nv_bfloat16 g_Vh[MT * HS_];
__device__ __align__(16) __nv_bfloat16 g_Vl[MT * HS_];
__device__ __align__(16) __nv_bfloat16 g_Wth[3][HS_ * C_];
__device__ __align__(16) __nv_bfloat16 g_Wtl[3][HS_ * C_];

// ---------------------------------------------------------------------------
// Helpers: mma.sync bf16 / ldmatrix / cp.async (baseline PTX, no tcgen05)
// ---------------------------------------------------------------------------
__device__ __forceinline__ uint32_t smem_u32(const void* p) {
    uint32_t a;
    asm("{ .reg .u64 t; cvta.to.shared.u64 t, %1; cvt.u32.u64 %0, t; }" : "=r"(a) : "l"(p));
    return a;
}
__device__ __forceinline__ void cp_async16(uint32_t dst, const void* src) {
    asm volatile("cp.async.ca.shared.global [%0], [%1], 16;" :: "r"(dst), "l"(src));
}
__device__ __forceinline__ void ldm_x4(uint32_t* r, uint32_t addr) {
    asm volatile("ldmatrix.sync.aligned.m8n8.x4.shared.b16 {%0,%1,%2,%3}, [%4];"
        : "=r"(r[0]), "=r"(r[1]), "=r"(r[2]), "=r"(r[3]) : "r"(addr));
}
__device__ __forceinline__ void ldm_x4_t(uint32_t* r, uint32_t addr) {
    asm volatile("ldmatrix.sync.aligned.m8n8.x4.trans.shared.b16 {%0,%1,%2,%3}, [%4];"
        : "=r"(r[0]), "=r"(r[1]), "=r"(r[2]), "=r"(r[3]) : "r"(addr));
}
__device__ __forceinline__ void mma_bf16(float* d, const uint32_t* a, uint32_t b0, uint32_t b1) {
    asm volatile("mma.sync.aligned.m16n8k16.row.col.f32.bf16.bf16.f32 "
        "{%0,%1,%2,%3}, {%4,%5,%6,%7}, {%8,%9}, {%0,%1,%2,%3};"
        : "+f"(d[0]), "+f"(d[1]), "+f"(d[2]), "+f"(d[3])
        : "r"(a[0]), "r"(a[1]), "r"(a[2]), "r"(a[3]), "r"(b0), "r"(b1));
}
__device__ __forceinline__ uint32_t pack_bf16(float a, float b) {
    __nv_bfloat162 t = __floats2bfloat162_rn(a, b);
    return *reinterpret_cast<uint32_t*>(&t);
}
__device__ __forceinline__ float bf16v(float x) {
    return __bfloat162float(__float2bfloat16(x));
}

// ---------------------------------------------------------------------------
// Prep: W [2048,128] fp32 -> W^T hi/lo bf16 [128,2048]
// ---------------------------------------------------------------------------
__global__ __launch_bounds__(256) void prep_w(
    const float* __restrict__ Wq, const float* __restrict__ Wk, const float* __restrict__ Wv)
{
    __shared__ float t[32][33];
    const int mi = blockIdx.z;
    const float* W = (mi == 0) ? Wq : ((mi == 1) ? Wk : Wv);
    const int k0 = blockIdx.x * 32, n0 = blockIdx.y * 32;
    const int tx = threadIdx.x & 31, ty = threadIdx.x >> 5;
#pragma unroll
    for (int i = 0; i < 32; i += 8)
        t[ty + i][tx] = W[(size_t)(k0 + ty + i) * HS_ + n0 + tx];
    __syncthreads();
#pragma unroll
    for (int i = 0; i < 32; i += 8) {
        float v = t[tx][ty + i];
        __nv_bfloat16 h = __float2bfloat16(v);
        __nv_bfloat16 l = __float2bfloat16(v - __bfloat162float(h));
        size_t o = (size_t)(n0 + ty + i) * C_ + (k0 + tx);
        g_Wth[mi][o] = h;
        g_Wtl[mi][o] = l;
    }
}

// ---------------------------------------------------------------------------
// QKV projection via mma.sync split-bf16 (unchanged from R4; writes hi/lo)
// ---------------------------------------------------------------------------
#define KC     64
#define NCHUNK (C_ / KC)
#define ASTRB  144
#define TILEB  (128 * ASTRB)
#define STAGEB (4 * TILEB)
#define SMEM_QKV (2 * STAGEB)

__global__ __launch_bounds__(256, 1) void qkv_mma(const float* __restrict__ x)
{
    extern __shared__ char smem[];
    const uint32_t sb = smem_u32(smem);
    const int tid  = threadIdx.x;
    const int lane = tid & 31, wid = tid >> 5;
    const int wm = wid >> 1, wn = wid & 1;
    const int m0 = blockIdx.x * 128;
    const int mi = blockIdx.y;

    const __nv_bfloat16* Wh = g_Wth[mi];
    const __nv_bfloat16* Wl = g_Wtl[mi];
    __nv_bfloat16* oh = (mi == 0) ? g_Qh : ((mi == 1) ? g_Kh : g_Vh);
    __nv_bfloat16* ol = (mi == 0) ? g_Ql : ((mi == 1) ? g_Kl : g_Vl);

    float acc[2][8][4];
#pragma unroll
    for (int i = 0; i < 2; i++)
#pragma unroll
        for (int j = 0; j < 8; j++)
#pragma unroll
            for (int k = 0; k < 4; k++) acc[i][j][k] = 0.0f;

    auto loadB = [&](int s, int c) {
        const uint32_t bh = sb + s * STAGEB + 2 * TILEB;
        const uint32_t bl = bh + TILEB;
#pragma unroll
        for (int t = 0; t < 8; t++) {
            const int idx = tid + t * 256;
            const int half = idx >> 10;
            const int w = idx & 1023;
            const int n = w >> 3, kk = w & 7;
            const __nv_bfloat16* base = half ? Wl : Wh;
            const char* src = (const char*)(base + (size_t)n * C_ + c * KC) + kk * 16;
            cp_async16((half ? bl : bh) + (uint32_t)(n * ASTRB + kk * 16), src);
        }
        asm volatile("cp.async.commit_group;");
    };
    auto loadA = [&](float4* ar, int c) {
#pragma unroll
        for (int t = 0; t < 8; t++) {
            const int idx = tid + t * 256;
            const int r = idx >> 4, f = idx & 15;
            ar[t] = *(const float4*)(x + (size_t)(m0 + r) * C_ + c * KC + f * 4);
        }
    };
    auto storeA = [&](int s, const float4* ar) {
        char* ah = smem + s * STAGEB;
        char* al = ah + TILEB;
#pragma unroll
        for (int t = 0; t < 8; t++) {
            const int idx = tid + t * 256;
            const int r = idx >> 4, f = idx & 15;
            float4 v = ar[t];
            __nv_bfloat16 hx = __float2bfloat16(v.x), hy = __float2bfloat16(v.y);
            __nv_bfloat16 hz = __float2bfloat16(v.z), hw = __float2bfloat16(v.w);
            uint2 hp, lp;
            hp.x = pack_bf16(__bfloat162float(hx), __bfloat162float(hy));
            hp.y = pack_bf16(__bfloat162float(hz), __bfloat162float(hw));
            lp.x = pack_bf16(v.x - __bfloat162float(hx), v.y - __bfloat162float(hy));
            lp.y = pack_bf16(v.z - __bfloat162float(hz), v.w - __bfloat162float(hw));
            const uint32_t o = (uint32_t)(r * ASTRB + f * 8);
            *(uint2*)(ah + o) = hp;
            *(uint2*)(al + o) = lp;
        }
    };

    const uint32_t aRowOff = (uint32_t)((wm * 32 + (lane & 15)) * ASTRB + (lane >> 4) * 16);
    const uint32_t bRowOff = (uint32_t)((wn * 64 + (lane & 15)) * ASTRB + (lane >> 4) * 16);

    float4 areg[8];
    loadB(0, 0);
    loadA(areg, 0);
    storeA(0, areg);
    asm volatile("cp.async.wait_group 0;" ::: "memory");
    __syncthreads();

    for (int c = 0; c < NCHUNK; c++) {
        const int s = c & 1;
        if (c + 1 < NCHUNK) {
            loadB(s ^ 1, c + 1);
            loadA(areg, c + 1);
        }
        const uint32_t ah = sb + s * STAGEB;
        const uint32_t al = ah + TILEB;
        const uint32_t bh = ah + 2 * TILEB;
        const uint32_t bl = ah + 3 * TILEB;

#pragma unroll
        for (int ks = 0; ks < 4; ks++) {
            uint32_t aF[2][4], aL[2][4], bF[4][4], bL[4][4];
#pragma unroll
            for (int mt = 0; mt < 2; mt++) {
                const uint32_t off = aRowOff + (uint32_t)(mt * 16 * ASTRB + ks * 32);
                ldm_x4(aF[mt], ah + off);
                ldm_x4(aL[mt], al + off);
            }
#pragma unroll
            for (int nt = 0; nt < 4; nt++) {
                const uint32_t off = bRowOff + (uint32_t)(nt * 16 * ASTRB + ks * 32);
                ldm_x4(bF[nt], bh + off);
                ldm_x4(bL[nt], bl + off);
            }
#pragma unroll
            for (int mt = 0; mt < 2; mt++) {
#pragma unroll
                for (int nt = 0; nt < 4; nt++) {
                    float* d0 = acc[mt][nt * 2];
                    float* d1 = acc[mt][nt * 2 + 1];
                    mma_bf16(d0, aF[mt], bF[nt][0], bF[nt][2]);
                    mma_bf16(d1, aF[mt], bF[nt][1], bF[nt][3]);
                    mma_bf16(d0, aF[mt], bL[nt][0], bL[nt][2]);
                    mma_bf16(d1, aF[mt], bL[nt][1], bL[nt][3]);
                    mma_bf16(d0, aL[mt], bF[nt][0], bF[nt][2]);
                    mma_bf16(d1, aL[mt], bF[nt][1], bF[nt][3]);
                }
            }
        }

        if (c + 1 < NCHUNK) {
            storeA(s ^ 1, areg);
            asm volatile("cp.async.wait_group 0;" ::: "memory");
        }
        __syncthreads();
    }

    const int g = lane >> 2, tg = lane & 3;
#pragma unroll
    for (int mt = 0; mt < 2; mt++) {
#pragma unroll
        for (int nf = 0; nf < 8; nf++) {
            const int n0 = wn * 64 + (nf >> 1) * 16 + (nf & 1) * 8 + tg * 2;
            const int r0 = m0 + wm * 32 + mt * 16 + g;
            float* d = acc[mt][nf];
            float h0 = bf16v(d[0]), h1 = bf16v(d[1]);
            float h2 = bf16v(d[2]), h3 = bf16v(d[3]);
            *(uint32_t*)(oh + (size_t)r0 * HS_ + n0)       = pack_bf16(h0, h1);
            *(uint32_t*)(ol + (size_t)r0 * HS_ + n0)       = pack_bf16(d[0] - h0, d[1] - h1);
            *(uint32_t*)(oh + (size_t)(r0 + 8) * HS_ + n0) = pack_bf16(h2, h3);
            *(uint32_t*)(ol + (size_t)(r0 + 8) * HS_ + n0) = pack_bf16(d[2] - h2, d[3] - h3);
        }
    }
}

// ---------------------------------------------------------------------------
// Flash attention, causal-balanced: BQ=64, BK=128, 8 warps = 4(m) x 2(n).
// CTA handles q-tile pair {p, 63-p}: every CTA does 32-33 k-tiles.
// n-split softmax stats exchanged via smem; partial O combined per q-tile.
// ---------------------------------------------------------------------------
#define RSTR   272
#define QTILE  (64 * RSTR)                 // 17408
#define KTILE  (128 * RSTR)                // 34816
#define OFF_QH 0
#define OFF_QL QTILE
#define OFF_KH (2 * QTILE)
#define OFF_KL (2 * QTILE + KTILE)
#define OFF_VH (2 * QTILE + 2 * KTILE)
#define OFF_VL (2 * QTILE + 3 * KTILE)
#define OFF_ST (2 * QTILE + 4 * KTILE)     // stats: 1024 B
#define SMEM_FL (OFF_ST + 1024)            // 175104
#define OCSTR  132                          // O-combine row stride (floats)

__global__ __launch_bounds__(256, 1) void flash_mma(float* __restrict__ y)
{
    extern __shared__ char fsm[];
    const uint32_t sb = smem_u32(fsm);
    float* Ocmb = (float*)fsm;                       // reuses Q area post-loop
    float* sMax = (float*)(fsm + OFF_ST);            // [64][2]
    float* sSum = (float*)(fsm + OFF_ST + 512);      // [64][2]

    const int tid = threadIdx.x, lane = tid & 31, wid = tid >> 5;
    const int wm = wid >> 1, wn = wid & 1;
    const int p = blockIdx.x, b = blockIdx.y;
    const float SCALE = 0.08838834764831845f;

    const int g = lane >> 2, tg = lane & 3;
    const uint32_t laneA = (uint32_t)((lane & 15) * RSTR + (lane >> 4) * 16);
    const int rloc0 = wm * 16 + g;                   // local rows rloc0, rloc0+8

    auto load64 = [&](uint32_t dst, const __nv_bfloat16* src) {
#pragma unroll
        for (int t = 0; t < 4; t++) {
            const int idx = tid + t * 256;
            const int r = idx >> 4, c = idx & 15;
            cp_async16(dst + (uint32_t)(r * RSTR + c * 16), (const char*)src + r * 256 + c * 16);
        }
    };
    auto load128 = [&](uint32_t dst, const __nv_bfloat16* src) {
#pragma unroll
        for (int t = 0; t < 8; t++) {
            const int idx = tid + t * 256;
            const int r = idx >> 4, c = idx & 15;
            cp_async16(dst + (uint32_t)(r * RSTR + c * 16), (const char*)src + r * 256 + c * 16);
        }
    };

    for (int pi = 0; pi < 2; pi++) {
        const int qt = pi ? (63 - p) : p;
        const int qbase = qt * 64;
        const int nkt = (qt >> 1) + 1;               // k-tiles of 128

        const size_t qoff = ((size_t)b * T_ + qbase) * HS_;
        load64(sb + OFF_QH, g_Qh + qoff);
        load64(sb + OFF_QL, g_Ql + qoff);
        asm volatile("cp.async.commit_group;");
        const size_t kbase0 = (size_t)b * T_ * HS_;
        load128(sb + OFF_KH, g_Kh + kbase0);
        load128(sb + OFF_KL, g_Kl + kbase0);
        asm volatile("cp.async.commit_group;");
        load128(sb + OFF_VH, g_Vh + kbase0);
        load128(sb + OFF_VL, g_Vl + kbase0);
        asm volatile("cp.async.commit_group;");

        float oacc[16][4];
#pragma unroll
        for (int i = 0; i < 16; i++)
#pragma unroll
            for (int j = 0; j < 4; j++) oacc[i][j] = 0.0f;
        float m0_ = -1e30f, m1_ = -1e30f, l0_ = 0.0f, l1_ = 0.0f;

        for (int kt = 0; kt < nkt; kt++) {
            asm volatile("cp.async.wait_group 1;" ::: "memory");   // Q(+K) / K
            __syncthreads();

            // ---- S = Q K^T over warp's 64 cols (wn half) ----
            float sacc[8][4];
#pragma unroll
            for (int i = 0; i < 8; i++)
#pragma unroll
                for (int j = 0; j < 4; j++) sacc[i][j] = 0.0f;

#pragma unroll
            for (int ks = 0; ks < 8; ks++) {
                uint32_t aH[4], aL[4];
                const uint32_t aoff = (uint32_t)(wm * 16 * RSTR) + laneA + ks * 32;
                ldm_x4(aH, sb + OFF_QH + aoff);
                ldm_x4(aL, sb + OFF_QL + aoff);
#pragma unroll
                for (int nt = 0; nt < 4; nt++) {
                    uint32_t kH[4], kL[4];
                    const uint32_t kro = (uint32_t)((wn * 64 + nt * 16) * RSTR) + laneA + ks * 32;
                    ldm_x4(kH, sb + OFF_KH + kro);
                    ldm_x4(kL, sb + OFF_KL + kro);
                    float* d0 = sacc[nt * 2];
                    float* d1 = sacc[nt * 2 + 1];
                    mma_bf16(d0, aH, kH[0], kH[2]);
                    mma_bf16(d1, aH, kH[1], kH[3]);
                    mma_bf16(d0, aH, kL[0], kL[2]);
                    mma_bf16(d1, aH, kL[1], kL[3]);
                    mma_bf16(d0, aL, kH[0], kH[2]);
                    mma_bf16(d1, aL, kH[1], kH[3]);
                }
            }
            __syncthreads();   // done reading K

            {   // prefetch next K (clamped)
                const int kn = (kt + 1 < nkt) ? (kt + 1) : (nkt - 1);
                const size_t ko = ((size_t)b * T_ + kn * 128) * HS_;
                load128(sb + OFF_KH, g_Kh + ko);
                load128(sb + OFF_KL, g_Kl + ko);
                asm volatile("cp.async.commit_group;");
            }
            asm volatile("cp.async.wait_group 1;" ::: "memory");   // V(kt)
            __syncthreads();

            // ---- online softmax with cross-wn exchange ----
            const int kb = kt * 128;
            const bool diag = (kt == nkt - 1);
            float mx0 = -1e30f, mx1 = -1e30f;
#pragma unroll
            for (int nt = 0; nt < 8; nt++) {
                const int c0 = kb + wn * 64 + nt * 8 + tg * 2;
#pragma unroll
                for (int j = 0; j < 2; j++) {
                    float v0 = sacc[nt][j] * SCALE;
                    float v1 = sacc[nt][2 + j] * SCALE;
                    if (diag && (c0 + j > qbase + rloc0))     v0 = -1e30f;
                    if (diag && (c0 + j > qbase + rloc0 + 8)) v1 = -1e30f;
                    sacc[nt][j]     = v0;
                    sacc[nt][2 + j] = v1;
                    mx0 = fmaxf(mx0, v0);
                    mx1 = fmaxf(mx1, v1);
                }
            }
            mx0 = fmaxf(mx0, __shfl_xor_sync(0xffffffffu, mx0, 1));
            mx0 = fmaxf(mx0, __shfl_xor_sync(0xffffffffu, mx0, 2));
            mx1 = fmaxf(mx1, __shfl_xor_sync(0xffffffffu, mx1, 1));
            mx1 = fmaxf(mx1, __shfl_xor_sync(0xffffffffu, mx1, 2));
            if (tg == 0) {
                sMax[(rloc0) * 2 + wn]     = mx0;
                sMax[(rloc0 + 8) * 2 + wn] = mx1;
            }
            __syncthreads();
            const float rmax0 = fmaxf(sMax[rloc0 * 2], sMax[rloc0 * 2 + 1]);
            const float rmax1 = fmaxf(sMax[(rloc0 + 8) * 2], sMax[(rloc0 + 8) * 2 + 1]);
            const float mn0 = fmaxf(m0_, rmax0), mn1 = fmaxf(m1_, rmax1);
            const float fac0 = __expf(m0_ - mn0), fac1 = __expf(m1_ - mn1);
            m0_ = mn0; m1_ = mn1;

            float rs0 = 0.0f, rs1 = 0.0f;
#pragma unroll
            for (int nt = 0; nt < 8; nt++) {
                float p0 = __expf(sacc[nt][0] - mn0);
                float p1 = __expf(sacc[nt][1] - mn0);
                float p2 = __expf(sacc[nt][2] - mn1);
                float p3 = __expf(sacc[nt][3] - mn1);
                sacc[nt][0] = p0; sacc[nt][1] = p1; sacc[nt][2] = p2; sacc[nt][3] = p3;
                rs0 += p0 + p1; rs1 += p2 + p3;
            }
            rs0 += __shfl_xor_sync(0xffffffffu, rs0, 1);
            rs0 += __shfl_xor_sync(0xffffffffu, rs0, 2);
            rs1 += __shfl_xor_sync(0xffffffffu, rs1, 1);
            rs1 += __shfl_xor_sync(0xffffffffu, rs1, 2);
            if (tg == 0) {
                sSum[(rloc0) * 2 + wn]     = rs0;
                sSum[(rloc0 + 8) * 2 + wn] = rs1;
            }
            __syncthreads();
            l0_ = l0_ * fac0 + sSum[rloc0 * 2] + sSum[rloc0 * 2 + 1];
            l1_ = l1_ * fac1 + sSum[(rloc0 + 8) * 2] + sSum[(rloc0 + 8) * 2 + 1];
#pragma unroll
            for (int dt = 0; dt < 16; dt++) {
                oacc[dt][0] *= fac0; oacc[dt][1] *= fac0;
                oacc[dt][2] *= fac1; oacc[dt][3] *= fac1;
            }

            // ---- O_partial += P V over warp's 64 k-rows ----
#pragma unroll
            for (int ks = 0; ks < 4; ks++) {
                float* s0 = sacc[ks * 2];
                float* s1 = sacc[ks * 2 + 1];
                const float h00 = bf16v(s0[0]), h01 = bf16v(s0[1]), h02 = bf16v(s0[2]), h03 = bf16v(s0[3]);
                const float h10 = bf16v(s1[0]), h11 = bf16v(s1[1]), h12 = bf16v(s1[2]), h13 = bf16v(s1[3]);
                uint32_t pah[4], pal[4];
                pah[0] = pack_bf16(h00, h01);
                pah[1] = pack_bf16(h02, h03);
                pah[2] = pack_bf16(h10, h11);
                pah[3] = pack_bf16(h12, h13);
                pal[0] = pack_bf16(s0[0] - h00, s0[1] - h01);
                pal[1] = pack_bf16(s0[2] - h02, s0[3] - h03);
                pal[2] = pack_bf16(s1[0] - h10, s1[1] - h11);
                pal[3] = pack_bf16(s1[2] - h12, s1[3] - h13);
#pragma unroll
                for (int dt = 0; dt < 8; dt++) {
                    uint32_t vH[4], vL[4];
                    const uint32_t voff = (uint32_t)((wn * 64 + ks * 16) * RSTR) + laneA + dt * 32;
                    ldm_x4_t(vH, sb + OFF_VH + voff);
                    ldm_x4_t(vL, sb + OFF_VL + voff);
                    float* d0 = oacc[dt * 2];
                    float* d1 = oacc[dt * 2 + 1];
                    mma_bf16(d0, pah, vH[0], vH[1]);
                    mma_bf16(d1, pah, vH[2], vH[3]);
                    mma_bf16(d0, pah, vL[0], vL[1]);
                    mma_bf16(d1, pah, vL[2], vL[3]);
                    mma_bf16(d0, pal, vH[0], vH[1]);
                    mma_bf16(d1, pal, vH[2], vH[3]);
                }
            }
            __syncthreads();   // done reading V

            {   // prefetch next V (clamped)
                const int kn = (kt + 1 < nkt) ? (kt + 1) : (nkt - 1);
                const size_t ko = ((size_t)b * T_ + kn * 128) * HS_;
                load128(sb + OFF_VH, g_Vh + ko);
                load128(sb + OFF_VL, g_Vl + ko);
                asm volatile("cp.async.commit_group;");
            }
        }

        asm volatile("cp.async.wait_group 0;" ::: "memory");
        __syncthreads();

        // ---- combine partial O across wn and store ----
        if (wn == 1) {
#pragma unroll
            for (int dt = 0; dt < 16; dt++) {
                const int c = dt * 8 + tg * 2;
                Ocmb[rloc0 * OCSTR + c]           = oacc[dt][0];
                Ocmb[rloc0 * OCSTR + c + 1]       = oacc[dt][1];
                Ocmb[(rloc0 + 8) * OCSTR + c]     = oacc[dt][2];
                Ocmb[(rloc0 + 8) * OCSTR + c + 1] = oacc[dt][3];
            }
        }
        __syncthreads();
        if (wn == 0) {
            const float inv0 = 1.0f / l0_, inv1 = 1.0f / l1_;
            float* y0 = y + ((size_t)b * T_ + qbase + rloc0) * HS_;
            float* y1 = y0 + 8 * HS_;
#pragma unroll
            for (int dt = 0; dt < 16; dt++) {
                const int c = dt * 8 + tg * 2;
                float a0 = (oacc[dt][0] + Ocmb[rloc0 * OCSTR + c]) * inv0;
                float a1 = (oacc[dt][1] + Ocmb[rloc0 * OCSTR + c + 1]) * inv0;
                float a2 = (oacc[dt][2] + Ocmb[(rloc0 + 8) * OCSTR + c]) * inv1;
                float a3 = (oacc[dt][3] + Ocmb[(rloc0 + 8) * OCSTR + c + 1]) * inv1;
                *(float2*)(y0 + c) = make_float2(a0, a1);
                *(float2*)(y1 + c) = make_float2(a2, a3);
            }
        }
        __syncthreads();   // protect smem reuse (Q area) for next q-tile
    }
}

// ---------------------------------------------------------------------------
extern "C" void kernel_launch(void* const* d_in, const int* in_sizes, int n_in,
                              void* d_out, int out_size)
{
    const float* x  = (const float*)d_in[0];
    const float* Wq = (const float*)d_in[1];
    const float* Wk = (const float*)d_in[2];
    const float* Wv = (const float*)d_in[3];
    float* y = (float*)d_out;
    (void)in_sizes; (void)n_in; (void)out_size;

    prep_w<<<dim3(64, 4, 3), 256>>>(Wq, Wk, Wv);

    cudaFuncSetAttribute(qkv_mma, cudaFuncAttributeMaxDynamicSharedMemorySize, SMEM_QKV);
    qkv_mma<<<dim3(128, 3), 256, SMEM_QKV>>>(x);

    cudaFuncSetAttribute(flash_mma, cudaFuncAttributeMaxDynamicSharedMemorySize, SMEM_FL);
    flash_mma<<<dim3(32, 4), 256, SMEM_FL>>>(y);
}

// round 6
// speedup vs baseline: 6.3150x; 2.2806x over previous
#include <cuda_runtime.h>
#include <cuda_fp16.h>
#include <cstdint>
#include <math.h>

#define B_  4
#define T_  4096
#define C_  2048
#define HS_ 128
#define MT  16384   // B_*T_

// Scratch (device globals per harness rules): Q/K/V and W^T as fp16
__device__ __align__(16) __half g_Qf[MT * HS_];
__device__ __align__(16) __half g_Kf[MT * HS_];
__device__ __align__(16) __half g_Vf[MT * HS_];
__device__ __align__(16) __half g_Wt[3][HS_ * C_];   // W^T, [n][k] K-major

// ---------------------------------------------------------------------------
// Helpers: mma.sync fp16 / ldmatrix / cp.async (baseline PTX, no tcgen05)
// ---------------------------------------------------------------------------
__device__ __forceinline__ uint32_t smem_u32(const void* p) {
    uint32_t a;
    asm("{ .reg .u64 t; cvta.to.shared.u64 t, %1; cvt.u32.u64 %0, t; }" : "=r"(a) : "l"(p));
    return a;
}
__device__ __forceinline__ void cp_async16(uint32_t dst, const void* src) {
    asm volatile("cp.async.ca.shared.global [%0], [%1], 16;" :: "r"(dst), "l"(src));
}
__device__ __forceinline__ void ldm_x4(uint32_t* r, uint32_t addr) {
    asm volatile("ldmatrix.sync.aligned.m8n8.x4.shared.b16 {%0,%1,%2,%3}, [%4];"
        : "=r"(r[0]), "=r"(r[1]), "=r"(r[2]), "=r"(r[3]) : "r"(addr));
}
__device__ __forceinline__ void ldm_x4_t(uint32_t* r, uint32_t addr) {
    asm volatile("ldmatrix.sync.aligned.m8n8.x4.trans.shared.b16 {%0,%1,%2,%3}, [%4];"
        : "=r"(r[0]), "=r"(r[1]), "=r"(r[2]), "=r"(r[3]) : "r"(addr));
}
__device__ __forceinline__ void mma_f16(float* d, const uint32_t* a, uint32_t b0, uint32_t b1) {
    asm volatile("mma.sync.aligned.m16n8k16.row.col.f32.f16.f16.f32 "
        "{%0,%1,%2,%3}, {%4,%5,%6,%7}, {%8,%9}, {%0,%1,%2,%3};"
        : "+f"(d[0]), "+f"(d[1]), "+f"(d[2]), "+f"(d[3])
        : "r"(a[0]), "r"(a[1]), "r"(a[2]), "r"(a[3]), "r"(b0), "r"(b1));
}
__device__ __forceinline__ uint32_t pack_h2(float a, float b) {
    __half2 t = __floats2half2_rn(a, b);
    return *reinterpret_cast<uint32_t*>(&t);
}

// ---------------------------------------------------------------------------
// Prep: W [2048,128] fp32 -> W^T fp16 [128,2048] (K-major for MMA B)
// ---------------------------------------------------------------------------
__global__ __launch_bounds__(256) void prep_w(
    const float* __restrict__ Wq, const float* __restrict__ Wk, const float* __restrict__ Wv)
{
    __shared__ float t[32][33];
    const int mi = blockIdx.z;
    const float* W = (mi == 0) ? Wq : ((mi == 1) ? Wk : Wv);
    const int k0 = blockIdx.x * 32, n0 = blockIdx.y * 32;
    const int tx = threadIdx.x & 31, ty = threadIdx.x >> 5;
#pragma unroll
    for (int i = 0; i < 32; i += 8)
        t[ty + i][tx] = W[(size_t)(k0 + ty + i) * HS_ + n0 + tx];
    __syncthreads();
#pragma unroll
    for (int i = 0; i < 32; i += 8) {
        float v = t[tx][ty + i];
        g_Wt[mi][(size_t)(n0 + ty + i) * C_ + (k0 + tx)] = __float2half(v);
    }
}

// ---------------------------------------------------------------------------
// QKV projection via single-pass fp16 mma.sync.
// CTA 128x128, 8 warps (4m x 2n), warp tile 32x64, K chunks 64, double buffer.
// grid (3, 128): matrix index fastest so same-m CTAs share x via L2.
// ---------------------------------------------------------------------------
#define KC     64
#define NCHUNK (C_ / KC)
#define ASTRB  144            // bytes per smem row (64 fp16 = 128 B + 16 pad)
#define TILEB  (128 * ASTRB)  // 18432
#define STAGEB (2 * TILEB)    // A + B
#define SMEM_QKV (2 * STAGEB) // 73728

__global__ __launch_bounds__(256, 1) void qkv_mma(const float* __restrict__ x)
{
    extern __shared__ char smem[];
    const uint32_t sb = smem_u32(smem);
    const int tid  = threadIdx.x;
    const int lane = tid & 31, wid = tid >> 5;
    const int wm = wid >> 1, wn = wid & 1;
    const int mi = blockIdx.x;               // matrix
    const int m0 = blockIdx.y * 128;

    const __half* Wt = g_Wt[mi];
    __half* out = (mi == 0) ? g_Qf : ((mi == 1) ? g_Kf : g_Vf);

    float acc[2][8][4];
#pragma unroll
    for (int i = 0; i < 2; i++)
#pragma unroll
        for (int j = 0; j < 8; j++)
#pragma unroll
            for (int k = 0; k < 4; k++) acc[i][j][k] = 0.0f;

    auto loadB = [&](int s, int c) {
        const uint32_t bq = sb + s * STAGEB + TILEB;
#pragma unroll
        for (int t = 0; t < 4; t++) {
            const int idx = tid + t * 256;
            const int n = idx >> 3, kk = idx & 7;
            const char* src = (const char*)(Wt + (size_t)n * C_ + c * KC) + kk * 16;
            cp_async16(bq + (uint32_t)(n * ASTRB + kk * 16), src);
        }
        asm volatile("cp.async.commit_group;");
    };
    auto loadA = [&](float4* ar, int c) {
#pragma unroll
        for (int t = 0; t < 8; t++) {
            const int idx = tid + t * 256;
            const int r = idx >> 4, f = idx & 15;
            ar[t] = *(const float4*)(x + (size_t)(m0 + r) * C_ + c * KC + f * 4);
        }
    };
    auto storeA = [&](int s, const float4* ar) {
        char* ad = smem + s * STAGEB;
#pragma unroll
        for (int t = 0; t < 8; t++) {
            const int idx = tid + t * 256;
            const int r = idx >> 4, f = idx & 15;
            float4 v = ar[t];
            uint2 hp;
            hp.x = pack_h2(v.x, v.y);
            hp.y = pack_h2(v.z, v.w);
            *(uint2*)(ad + (uint32_t)(r * ASTRB + f * 8)) = hp;
        }
    };

    const uint32_t aRowOff = (uint32_t)((wm * 32 + (lane & 15)) * ASTRB + (lane >> 4) * 16);
    const uint32_t bRowOff = (uint32_t)((wn * 64 + (lane & 15)) * ASTRB + (lane >> 4) * 16);

    float4 areg[8];
    loadB(0, 0);
    loadA(areg, 0);
    storeA(0, areg);
    asm volatile("cp.async.wait_group 0;" ::: "memory");
    __syncthreads();

    for (int c = 0; c < NCHUNK; c++) {
        const int s = c & 1;
        if (c + 1 < NCHUNK) {
            loadB(s ^ 1, c + 1);
            loadA(areg, c + 1);
        }
        const uint32_t ah = sb + s * STAGEB;
        const uint32_t bq = ah + TILEB;

#pragma unroll
        for (int ks = 0; ks < 4; ks++) {
            uint32_t aF[2][4], bF[4][4];
#pragma unroll
            for (int mt = 0; mt < 2; mt++)
                ldm_x4(aF[mt], ah + aRowOff + (uint32_t)(mt * 16 * ASTRB + ks * 32));
#pragma unroll
            for (int nt = 0; nt < 4; nt++)
                ldm_x4(bF[nt], bq + bRowOff + (uint32_t)(nt * 16 * ASTRB + ks * 32));
#pragma unroll
            for (int mt = 0; mt < 2; mt++) {
#pragma unroll
                for (int nt = 0; nt < 4; nt++) {
                    mma_f16(acc[mt][nt * 2],     aF[mt], bF[nt][0], bF[nt][2]);
                    mma_f16(acc[mt][nt * 2 + 1], aF[mt], bF[nt][1], bF[nt][3]);
                }
            }
        }

        if (c + 1 < NCHUNK) {
            storeA(s ^ 1, areg);
            asm volatile("cp.async.wait_group 0;" ::: "memory");
        }
        __syncthreads();
    }

    // Epilogue: fp32 acc -> fp16
    const int g = lane >> 2, tg = lane & 3;
#pragma unroll
    for (int mt = 0; mt < 2; mt++) {
#pragma unroll
        for (int nf = 0; nf < 8; nf++) {
            const int n0 = wn * 64 + (nf >> 1) * 16 + (nf & 1) * 8 + tg * 2;
            const int r0 = m0 + wm * 32 + mt * 16 + g;
            float* d = acc[mt][nf];
            *(uint32_t*)(out + (size_t)r0 * HS_ + n0)       = pack_h2(d[0], d[1]);
            *(uint32_t*)(out + (size_t)(r0 + 8) * HS_ + n0) = pack_h2(d[2], d[3]);
        }
    }
}

// ---------------------------------------------------------------------------
// Flash attention, causal-balanced, single-pass fp16 mma.
// BQ=64, BK=128, 8 warps = 4(m) x 2(n). CTA handles q-tile pair {p, 63-p}.
// ---------------------------------------------------------------------------
#define RSTR   272
#define QTILE  (64 * RSTR)                 // 17408
#define KTILE  (128 * RSTR)                // 34816
#define OFF_Q  0
#define OFF_K  QTILE
#define OFF_V  (QTILE + KTILE)
#define OFF_ST (QTILE + 2 * KTILE)
#define SMEM_FL (OFF_ST + 1024)            // 88064
#define OCSTR  132

__global__ __launch_bounds__(256, 1) void flash_mma(float* __restrict__ y)
{
    extern __shared__ char fsm[];
    const uint32_t sb = smem_u32(fsm);
    float* Ocmb = (float*)fsm;                       // reuses Q+K area post-loop
    float* sMax = (float*)(fsm + OFF_ST);
    float* sSum = (float*)(fsm + OFF_ST + 512);

    const int tid = threadIdx.x, lane = tid & 31, wid = tid >> 5;
    const int wm = wid >> 1, wn = wid & 1;
    const int p = blockIdx.x, b = blockIdx.y;
    const float SCALE = 0.08838834764831845f;

    const int g = lane >> 2, tg = lane & 3;
    const uint32_t laneA = (uint32_t)((lane & 15) * RSTR + (lane >> 4) * 16);
    const int rloc0 = wm * 16 + g;

    auto load64 = [&](uint32_t dst, const __half* src) {
#pragma unroll
        for (int t = 0; t < 4; t++) {
            const int idx = tid + t * 256;
            const int r = idx >> 4, c = idx & 15;
            cp_async16(dst + (uint32_t)(r * RSTR + c * 16), (const char*)src + r * 256 + c * 16);
        }
    };
    auto load128 = [&](uint32_t dst, const __half* src) {
#pragma unroll
        for (int t = 0; t < 8; t++) {
            const int idx = tid + t * 256;
            const int r = idx >> 4, c = idx & 15;
            cp_async16(dst + (uint32_t)(r * RSTR + c * 16), (const char*)src + r * 256 + c * 16);
        }
    };

    for (int pi = 0; pi < 2; pi++) {
        const int qt = pi ? (63 - p) : p;
        const int qbase = qt * 64;
        const int nkt = (qt >> 1) + 1;

        load64(sb + OFF_Q, g_Qf + ((size_t)b * T_ + qbase) * HS_);
        asm volatile("cp.async.commit_group;");
        const size_t kbase0 = (size_t)b * T_ * HS_;
        load128(sb + OFF_K, g_Kf + kbase0);
        asm volatile("cp.async.commit_group;");
        load128(sb + OFF_V, g_Vf + kbase0);
        asm volatile("cp.async.commit_group;");

        float oacc[16][4];
#pragma unroll
        for (int i = 0; i < 16; i++)
#pragma unroll
            for (int j = 0; j < 4; j++) oacc[i][j] = 0.0f;
        float m0_ = -1e30f, m1_ = -1e30f, l0_ = 0.0f, l1_ = 0.0f;

        for (int kt = 0; kt < nkt; kt++) {
            asm volatile("cp.async.wait_group 1;" ::: "memory");   // Q+K ready
            __syncthreads();

            // ---- S = Q K^T over warp's 64 cols (wn half) ----
            float sacc[8][4];
#pragma unroll
            for (int i = 0; i < 8; i++)
#pragma unroll
                for (int j = 0; j < 4; j++) sacc[i][j] = 0.0f;

#pragma unroll
            for (int ks = 0; ks < 8; ks++) {
                uint32_t aH[4];
                ldm_x4(aH, sb + OFF_Q + (uint32_t)(wm * 16 * RSTR) + laneA + ks * 32);
#pragma unroll
                for (int nt = 0; nt < 4; nt++) {
                    uint32_t kH[4];
                    ldm_x4(kH, sb + OFF_K + (uint32_t)((wn * 64 + nt * 16) * RSTR) + laneA + ks * 32);
                    mma_f16(sacc[nt * 2],     aH, kH[0], kH[2]);
                    mma_f16(sacc[nt * 2 + 1], aH, kH[1], kH[3]);
                }
            }
            __syncthreads();   // done reading K

            {   // prefetch next K (clamped)
                const int kn = (kt + 1 < nkt) ? (kt + 1) : (nkt - 1);
                load128(sb + OFF_K, g_Kf + ((size_t)b * T_ + kn * 128) * HS_);
                asm volatile("cp.async.commit_group;");
            }
            asm volatile("cp.async.wait_group 1;" ::: "memory");   // V(kt)
            __syncthreads();

            // ---- online softmax with cross-wn exchange ----
            const int kb = kt * 128;
            const bool diag = (kt == nkt - 1);
            float mx0 = -1e30f, mx1 = -1e30f;
#pragma unroll
            for (int nt = 0; nt < 8; nt++) {
                const int c0 = kb + wn * 64 + nt * 8 + tg * 2;
#pragma unroll
                for (int j = 0; j < 2; j++) {
                    float v0 = sacc[nt][j] * SCALE;
                    float v1 = sacc[nt][2 + j] * SCALE;
                    if (diag && (c0 + j > qbase + rloc0))     v0 = -1e30f;
                    if (diag && (c0 + j > qbase + rloc0 + 8)) v1 = -1e30f;
                    sacc[nt][j]     = v0;
                    sacc[nt][2 + j] = v1;
                    mx0 = fmaxf(mx0, v0);
                    mx1 = fmaxf(mx1, v1);
                }
            }
            mx0 = fmaxf(mx0, __shfl_xor_sync(0xffffffffu, mx0, 1));
            mx0 = fmaxf(mx0, __shfl_xor_sync(0xffffffffu, mx0, 2));
            mx1 = fmaxf(mx1, __shfl_xor_sync(0xffffffffu, mx1, 1));
            mx1 = fmaxf(mx1, __shfl_xor_sync(0xffffffffu, mx1, 2));
            if (tg == 0) {
                sMax[(rloc0) * 2 + wn]     = mx0;
                sMax[(rloc0 + 8) * 2 + wn] = mx1;
            }
            __syncthreads();
            const float rmax0 = fmaxf(sMax[rloc0 * 2], sMax[rloc0 * 2 + 1]);
            const float rmax1 = fmaxf(sMax[(rloc0 + 8) * 2], sMax[(rloc0 + 8) * 2 + 1]);
            const float mn0 = fmaxf(m0_, rmax0), mn1 = fmaxf(m1_, rmax1);
            const float fac0 = __expf(m0_ - mn0), fac1 = __expf(m1_ - mn1);
            m0_ = mn0; m1_ = mn1;

            float rs0 = 0.0f, rs1 = 0.0f;
#pragma unroll
            for (int nt = 0; nt < 8; nt++) {
                float p0 = __expf(sacc[nt][0] - mn0);
                float p1 = __expf(sacc[nt][1] - mn0);
                float p2 = __expf(sacc[nt][2] - mn1);
                float p3 = __expf(sacc[nt][3] - mn1);
                sacc[nt][0] = p0; sacc[nt][1] = p1; sacc[nt][2] = p2; sacc[nt][3] = p3;
                rs0 += p0 + p1; rs1 += p2 + p3;
            }
            rs0 += __shfl_xor_sync(0xffffffffu, rs0, 1);
            rs0 += __shfl_xor_sync(0xffffffffu, rs0, 2);
            rs1 += __shfl_xor_sync(0xffffffffu, rs1, 1);
            rs1 += __shfl_xor_sync(0xffffffffu, rs1, 2);
            if (tg == 0) {
                sSum[(rloc0) * 2 + wn]     = rs0;
                sSum[(rloc0 + 8) * 2 + wn] = rs1;
            }
            __syncthreads();
            l0_ = l0_ * fac0 + sSum[rloc0 * 2] + sSum[rloc0 * 2 + 1];
            l1_ = l1_ * fac1 + sSum[(rloc0 + 8) * 2] + sSum[(rloc0 + 8) * 2 + 1];
#pragma unroll
            for (int dt = 0; dt < 16; dt++) {
                oacc[dt][0] *= fac0; oacc[dt][1] *= fac0;
                oacc[dt][2] *= fac1; oacc[dt][3] *= fac1;
            }

            // ---- O_partial += P V over warp's 64 k-rows ----
#pragma unroll
            for (int ks = 0; ks < 4; ks++) {
                float* s0 = sacc[ks * 2];
                float* s1 = sacc[ks * 2 + 1];
                uint32_t pa[4];
                pa[0] = pack_h2(s0[0], s0[1]);
                pa[1] = pack_h2(s0[2], s0[3]);
                pa[2] = pack_h2(s1[0], s1[1]);
                pa[3] = pack_h2(s1[2], s1[3]);
#pragma unroll
                for (int dt = 0; dt < 8; dt++) {
                    uint32_t vH[4];
                    ldm_x4_t(vH, sb + OFF_V + (uint32_t)((wn * 64 + ks * 16) * RSTR) + laneA + dt * 32);
                    mma_f16(oacc[dt * 2],     pa, vH[0], vH[1]);
                    mma_f16(oacc[dt * 2 + 1], pa, vH[2], vH[3]);
                }
            }
            __syncthreads();   // done reading V

            {   // prefetch next V (clamped)
                const int kn = (kt + 1 < nkt) ? (kt + 1) : (nkt - 1);
                load128(sb + OFF_V, g_Vf + ((size_t)b * T_ + kn * 128) * HS_);
                asm volatile("cp.async.commit_group;");
            }
        }

        asm volatile("cp.async.wait_group 0;" ::: "memory");
        __syncthreads();

        // ---- combine partial O across wn and store ----
        if (wn == 1) {
#pragma unroll
            for (int dt = 0; dt < 16; dt++) {
                const int c = dt * 8 + tg * 2;
                Ocmb[rloc0 * OCSTR + c]           = oacc[dt][0];
                Ocmb[rloc0 * OCSTR + c + 1]       = oacc[dt][1];
                Ocmb[(rloc0 + 8) * OCSTR + c]     = oacc[dt][2];
                Ocmb[(rloc0 + 8) * OCSTR + c + 1] = oacc[dt][3];
            }
        }
        __syncthreads();
        if (wn == 0) {
            const float inv0 = 1.0f / l0_, inv1 = 1.0f / l1_;
            float* y0 = y + ((size_t)b * T_ + qbase + rloc0) * HS_;
            float* y1 = y0 + 8 * HS_;
#pragma unroll
            for (int dt = 0; dt < 16; dt++) {
                const int c = dt * 8 + tg * 2;
                float a0 = (oacc[dt][0] + Ocmb[rloc0 * OCSTR + c]) * inv0;
                float a1 = (oacc[dt][1] + Ocmb[rloc0 * OCSTR + c + 1]) * inv0;
                float a2 = (oacc[dt][2] + Ocmb[(rloc0 + 8) * OCSTR + c]) * inv1;
                float a3 = (oacc[dt][3] + Ocmb[(rloc0 + 8) * OCSTR + c + 1]) * inv1;
                *(float2*)(y0 + c) = make_float2(a0, a1);
                *(float2*)(y1 + c) = make_float2(a2, a3);
            }
        }
        __syncthreads();   // protect smem reuse for next q-tile
    }
}

// ---------------------------------------------------------------------------
extern "C" void kernel_launch(void* const* d_in, const int* in_sizes, int n_in,
                              void* d_out, int out_size)
{
    const float* x  = (const float*)d_in[0];
    const float* Wq = (const float*)d_in[1];
    const float* Wk = (const float*)d_in[2];
    const float* Wv = (const float*)d_in[3];
    float* y = (float*)d_out;
    (void)in_sizes; (void)n_in; (void)out_size;

    prep_w<<<dim3(64, 4, 3), 256>>>(Wq, Wk, Wv);

    cudaFuncSetAttribute(qkv_mma, cudaFuncAttributeMaxDynamicSharedMemorySize, SMEM_QKV);
    qkv_mma<<<dim3(3, 128), 256, SMEM_QKV>>>(x);

    cudaFuncSetAttribute(flash_mma, cudaFuncAttributeMaxDynamicSharedMemorySize, SMEM_FL);
    flash_mma<<<dim3(32, 4), 256, SMEM_FL>>>(y);
}

// round 7
// speedup vs baseline: 6.3201x; 1.0008x over previous
#include <cuda_runtime.h>
#include <cuda_fp16.h>
#include <cstdint>
#include <math.h>

#define B_  4
#define T_  4096
#define C_  2048
#define HS_ 128
#define MT  16384   // B_*T_

// Scratch (device globals per harness rules): Q/K/V and W^T as fp16
__device__ __align__(16) __half g_Qf[MT * HS_];
__device__ __align__(16) __half g_Kf[MT * HS_];
__device__ __align__(16) __half g_Vf[MT * HS_];
__device__ __align__(16) __half g_Wt[3][HS_ * C_];   // W^T, [n][k] K-major

// ---------------------------------------------------------------------------
// Helpers: mma.sync fp16 / ldmatrix / cp.async (baseline PTX, no tcgen05)
// ---------------------------------------------------------------------------
__device__ __forceinline__ uint32_t smem_u32(const void* p) {
    uint32_t a;
    asm("{ .reg .u64 t; cvta.to.shared.u64 t, %1; cvt.u32.u64 %0, t; }" : "=r"(a) : "l"(p));
    return a;
}
__device__ __forceinline__ void cp_async16(uint32_t dst, const void* src) {
    asm volatile("cp.async.ca.shared.global [%0], [%1], 16;" :: "r"(dst), "l"(src));
}
__device__ __forceinline__ void ldm_x4(uint32_t* r, uint32_t addr) {
    asm volatile("ldmatrix.sync.aligned.m8n8.x4.shared.b16 {%0,%1,%2,%3}, [%4];"
        : "=r"(r[0]), "=r"(r[1]), "=r"(r[2]), "=r"(r[3]) : "r"(addr));
}
__device__ __forceinline__ void ldm_x4_t(uint32_t* r, uint32_t addr) {
    asm volatile("ldmatrix.sync.aligned.m8n8.x4.trans.shared.b16 {%0,%1,%2,%3}, [%4];"
        : "=r"(r[0]), "=r"(r[1]), "=r"(r[2]), "=r"(r[3]) : "r"(addr));
}
__device__ __forceinline__ void mma_f16(float* d, const uint32_t* a, uint32_t b0, uint32_t b1) {
    asm volatile("mma.sync.aligned.m16n8k16.row.col.f32.f16.f16.f32 "
        "{%0,%1,%2,%3}, {%4,%5,%6,%7}, {%8,%9}, {%0,%1,%2,%3};"
        : "+f"(d[0]), "+f"(d[1]), "+f"(d[2]), "+f"(d[3])
        : "r"(a[0]), "r"(a[1]), "r"(a[2]), "r"(a[3]), "r"(b0), "r"(b1));
}
__device__ __forceinline__ uint32_t pack_h2(float a, float b) {
    __half2 t = __floats2half2_rn(a, b);
    return *reinterpret_cast<uint32_t*>(&t);
}

// ---------------------------------------------------------------------------
// Prep: W [2048,128] fp32 -> W^T fp16 [128,2048] (K-major for MMA B)
// ---------------------------------------------------------------------------
__global__ __launch_bounds__(256) void prep_w(
    const float* __restrict__ Wq, const float* __restrict__ Wk, const float* __restrict__ Wv)
{
    __shared__ float t[32][33];
    const int mi = blockIdx.z;
    const float* W = (mi == 0) ? Wq : ((mi == 1) ? Wk : Wv);
    const int k0 = blockIdx.x * 32, n0 = blockIdx.y * 32;
    const int tx = threadIdx.x & 31, ty = threadIdx.x >> 5;
#pragma unroll
    for (int i = 0; i < 32; i += 8)
        t[ty + i][tx] = W[(size_t)(k0 + ty + i) * HS_ + n0 + tx];
    __syncthreads();
#pragma unroll
    for (int i = 0; i < 32; i += 8) {
        float v = t[tx][ty + i];
        g_Wt[mi][(size_t)(n0 + ty + i) * C_ + (k0 + tx)] = __float2half(v);
    }
}

// ---------------------------------------------------------------------------
// QKV projection via single-pass fp16 mma.sync. Occupancy 2.
// CTA 128x128, 8 warps (4m x 2n), warp tile 32x64, K chunks 64, double buffer.
// grid (3, 128): matrix index fastest so same-m CTAs share x via L2.
// ---------------------------------------------------------------------------
#define KC     64
#define NCHUNK (C_ / KC)
#define ASTRB  144            // bytes per smem row (64 fp16 = 128 B + 16 pad)
#define TILEB  (128 * ASTRB)  // 18432
#define STAGEB (2 * TILEB)    // A + B
#define SMEM_QKV (2 * STAGEB) // 73728

__global__ __launch_bounds__(256, 2) void qkv_mma(const float* __restrict__ x)
{
    extern __shared__ char smem[];
    const uint32_t sb = smem_u32(smem);
    const int tid  = threadIdx.x;
    const int lane = tid & 31, wid = tid >> 5;
    const int wm = wid >> 1, wn = wid & 1;
    const int mi = blockIdx.x;               // matrix
    const int m0 = blockIdx.y * 128;

    const __half* Wt = g_Wt[mi];
    __half* out = (mi == 0) ? g_Qf : ((mi == 1) ? g_Kf : g_Vf);

    float acc[2][8][4];
#pragma unroll
    for (int i = 0; i < 2; i++)
#pragma unroll
        for (int j = 0; j < 8; j++)
#pragma unroll
            for (int k = 0; k < 4; k++) acc[i][j][k] = 0.0f;

    auto loadB = [&](int s, int c) {
        const uint32_t bq = sb + s * STAGEB + TILEB;
#pragma unroll
        for (int t = 0; t < 4; t++) {
            const int idx = tid + t * 256;
            const int n = idx >> 3, kk = idx & 7;
            const char* src = (const char*)(Wt + (size_t)n * C_ + c * KC) + kk * 16;
            cp_async16(bq + (uint32_t)(n * ASTRB + kk * 16), src);
        }
        asm volatile("cp.async.commit_group;");
    };
    // load A (fp32) and convert to fp16 pairs immediately (halves staging regs)
    auto loadA = [&](uint2* ar, int c) {
#pragma unroll
        for (int t = 0; t < 8; t++) {
            const int idx = tid + t * 256;
            const int r = idx >> 4, f = idx & 15;
            float4 v = *(const float4*)(x + (size_t)(m0 + r) * C_ + c * KC + f * 4);
            ar[t].x = pack_h2(v.x, v.y);
            ar[t].y = pack_h2(v.z, v.w);
        }
    };
    auto storeA = [&](int s, const uint2* ar) {
        char* ad = smem + s * STAGEB;
#pragma unroll
        for (int t = 0; t < 8; t++) {
            const int idx = tid + t * 256;
            const int r = idx >> 4, f = idx & 15;
            *(uint2*)(ad + (uint32_t)(r * ASTRB + f * 8)) = ar[t];
        }
    };

    const uint32_t aRowOff = (uint32_t)((wm * 32 + (lane & 15)) * ASTRB + (lane >> 4) * 16);
    const uint32_t bRowOff = (uint32_t)((wn * 64 + (lane & 15)) * ASTRB + (lane >> 4) * 16);

    uint2 areg[8];
    loadB(0, 0);
    loadA(areg, 0);
    storeA(0, areg);
    asm volatile("cp.async.wait_group 0;" ::: "memory");
    __syncthreads();

    for (int c = 0; c < NCHUNK; c++) {
        const int s = c & 1;
        if (c + 1 < NCHUNK) {
            loadB(s ^ 1, c + 1);
            loadA(areg, c + 1);
        }
        const uint32_t ah = sb + s * STAGEB;
        const uint32_t bq = ah + TILEB;

#pragma unroll
        for (int ks = 0; ks < 4; ks++) {
            uint32_t aF[2][4], bF[4][4];
#pragma unroll
            for (int mt = 0; mt < 2; mt++)
                ldm_x4(aF[mt], ah + aRowOff + (uint32_t)(mt * 16 * ASTRB + ks * 32));
#pragma unroll
            for (int nt = 0; nt < 4; nt++)
                ldm_x4(bF[nt], bq + bRowOff + (uint32_t)(nt * 16 * ASTRB + ks * 32));
#pragma unroll
            for (int mt = 0; mt < 2; mt++) {
#pragma unroll
                for (int nt = 0; nt < 4; nt++) {
                    mma_f16(acc[mt][nt * 2],     aF[mt], bF[nt][0], bF[nt][2]);
                    mma_f16(acc[mt][nt * 2 + 1], aF[mt], bF[nt][1], bF[nt][3]);
                }
            }
        }

        if (c + 1 < NCHUNK) {
            storeA(s ^ 1, areg);
            asm volatile("cp.async.wait_group 0;" ::: "memory");
        }
        __syncthreads();
    }

    // Epilogue: fp32 acc -> fp16
    const int g = lane >> 2, tg = lane & 3;
#pragma unroll
    for (int mt = 0; mt < 2; mt++) {
#pragma unroll
        for (int nf = 0; nf < 8; nf++) {
            const int n0 = wn * 64 + (nf >> 1) * 16 + (nf & 1) * 8 + tg * 2;
            const int r0 = m0 + wm * 32 + mt * 16 + g;
            float* d = acc[mt][nf];
            *(uint32_t*)(out + (size_t)r0 * HS_ + n0)       = pack_h2(d[0], d[1]);
            *(uint32_t*)(out + (size_t)(r0 + 8) * HS_ + n0) = pack_h2(d[2], d[3]);
        }
    }
}

// ---------------------------------------------------------------------------
// Flash attention, causal-balanced, fp16 mma, warp-local online softmax.
// BQ=64, BK=128, 8 warps = 4(m) x 2(n). CTA handles q-tile pair {p, 63-p}.
// Each wn-half keeps independent (m,l,O); combined once at the end.
// ---------------------------------------------------------------------------
#define RSTR   272
#define QTILE  (64 * RSTR)                 // 17408
#define KTILE  (128 * RSTR)                // 34816
#define OFF_Q  0
#define OFF_K  QTILE
#define OFF_V  (QTILE + KTILE)
#define OFF_ST (QTILE + 2 * KTILE)
#define SMEM_FL (OFF_ST + 1024)            // 88064
#define OCSTR  132

__global__ __launch_bounds__(256, 1) void flash_mma(float* __restrict__ y)
{
    extern __shared__ char fsm[];
    const uint32_t sb = smem_u32(fsm);
    float* Ocmb = (float*)fsm;                       // reuses Q+K area post-loop
    float* sMax = (float*)(fsm + OFF_ST);            // [64] wn=1 m values
    float* sSum = (float*)(fsm + OFF_ST + 512);      // [64] wn=1 l values

    const int tid = threadIdx.x, lane = tid & 31, wid = tid >> 5;
    const int wm = wid >> 1, wn = wid & 1;
    const int p = blockIdx.x, b = blockIdx.y;
    const float SCALE = 0.08838834764831845f;

    const int g = lane >> 2, tg = lane & 3;
    const uint32_t laneA = (uint32_t)((lane & 15) * RSTR + (lane >> 4) * 16);
    const int rloc0 = wm * 16 + g;

    auto load64 = [&](uint32_t dst, const __half* src) {
#pragma unroll
        for (int t = 0; t < 4; t++) {
            const int idx = tid + t * 256;
            const int r = idx >> 4, c = idx & 15;
            cp_async16(dst + (uint32_t)(r * RSTR + c * 16), (const char*)src + r * 256 + c * 16);
        }
    };
    auto load128 = [&](uint32_t dst, const __half* src) {
#pragma unroll
        for (int t = 0; t < 8; t++) {
            const int idx = tid + t * 256;
            const int r = idx >> 4, c = idx & 15;
            cp_async16(dst + (uint32_t)(r * RSTR + c * 16), (const char*)src + r * 256 + c * 16);
        }
    };

    for (int pi = 0; pi < 2; pi++) {
        const int qt = pi ? (63 - p) : p;
        const int qbase = qt * 64;
        const int nkt = (qt >> 1) + 1;

        load64(sb + OFF_Q, g_Qf + ((size_t)b * T_ + qbase) * HS_);
        asm volatile("cp.async.commit_group;");
        const size_t kbase0 = (size_t)b * T_ * HS_;
        load128(sb + OFF_K, g_Kf + kbase0);
        asm volatile("cp.async.commit_group;");
        load128(sb + OFF_V, g_Vf + kbase0);
        asm volatile("cp.async.commit_group;");

        float oacc[16][4];
#pragma unroll
        for (int i = 0; i < 16; i++)
#pragma unroll
            for (int j = 0; j < 4; j++) oacc[i][j] = 0.0f;
        float m0_ = -1e30f, m1_ = -1e30f, l0_ = 0.0f, l1_ = 0.0f;

        for (int kt = 0; kt < nkt; kt++) {
            asm volatile("cp.async.wait_group 1;" ::: "memory");   // Q+K ready
            __syncthreads();

            // ---- S = Q K^T over warp's 64 cols (wn half) ----
            float sacc[8][4];
#pragma unroll
            for (int i = 0; i < 8; i++)
#pragma unroll
                for (int j = 0; j < 4; j++) sacc[i][j] = 0.0f;

#pragma unroll
            for (int ks = 0; ks < 8; ks++) {
                uint32_t aH[4];
                ldm_x4(aH, sb + OFF_Q + (uint32_t)(wm * 16 * RSTR) + laneA + ks * 32);
#pragma unroll
                for (int nt = 0; nt < 4; nt++) {
                    uint32_t kH[4];
                    ldm_x4(kH, sb + OFF_K + (uint32_t)((wn * 64 + nt * 16) * RSTR) + laneA + ks * 32);
                    mma_f16(sacc[nt * 2],     aH, kH[0], kH[2]);
                    mma_f16(sacc[nt * 2 + 1], aH, kH[1], kH[3]);
                }
            }
            __syncthreads();   // done reading K

            {   // prefetch next K (skipped work on last iter, commit kept)
                if (kt + 1 < nkt)
                    load128(sb + OFF_K, g_Kf + ((size_t)b * T_ + (kt + 1) * 128) * HS_);
                asm volatile("cp.async.commit_group;");
            }

            // ---- warp-local online softmax (overlaps V arrival) ----
            const int kb = kt * 128;
            const bool diag = (kt == nkt - 1);
            float mx0 = -1e30f, mx1 = -1e30f;
#pragma unroll
            for (int nt = 0; nt < 8; nt++) {
                const int c0 = kb + wn * 64 + nt * 8 + tg * 2;
#pragma unroll
                for (int j = 0; j < 2; j++) {
                    float v0 = sacc[nt][j] * SCALE;
                    float v1 = sacc[nt][2 + j] * SCALE;
                    if (diag && (c0 + j > qbase + rloc0))     v0 = -1e30f;
                    if (diag && (c0 + j > qbase + rloc0 + 8)) v1 = -1e30f;
                    sacc[nt][j]     = v0;
                    sacc[nt][2 + j] = v1;
                    mx0 = fmaxf(mx0, v0);
                    mx1 = fmaxf(mx1, v1);
                }
            }
            mx0 = fmaxf(mx0, __shfl_xor_sync(0xffffffffu, mx0, 1));
            mx0 = fmaxf(mx0, __shfl_xor_sync(0xffffffffu, mx0, 2));
            mx1 = fmaxf(mx1, __shfl_xor_sync(0xffffffffu, mx1, 1));
            mx1 = fmaxf(mx1, __shfl_xor_sync(0xffffffffu, mx1, 2));

            const float mn0 = fmaxf(m0_, mx0), mn1 = fmaxf(m1_, mx1);
            const float fac0 = __expf(m0_ - mn0), fac1 = __expf(m1_ - mn1);
            m0_ = mn0; m1_ = mn1;

            float rs0 = 0.0f, rs1 = 0.0f;
#pragma unroll
            for (int nt = 0; nt < 8; nt++) {
                float p0 = __expf(sacc[nt][0] - mn0);
                float p1 = __expf(sacc[nt][1] - mn0);
                float p2 = __expf(sacc[nt][2] - mn1);
                float p3 = __expf(sacc[nt][3] - mn1);
                sacc[nt][0] = p0; sacc[nt][1] = p1; sacc[nt][2] = p2; sacc[nt][3] = p3;
                rs0 += p0 + p1; rs1 += p2 + p3;
            }
            rs0 += __shfl_xor_sync(0xffffffffu, rs0, 1);
            rs0 += __shfl_xor_sync(0xffffffffu, rs0, 2);
            rs1 += __shfl_xor_sync(0xffffffffu, rs1, 1);
            rs1 += __shfl_xor_sync(0xffffffffu, rs1, 2);
            l0_ = l0_ * fac0 + rs0;
            l1_ = l1_ * fac1 + rs1;
#pragma unroll
            for (int dt = 0; dt < 16; dt++) {
                oacc[dt][0] *= fac0; oacc[dt][1] *= fac0;
                oacc[dt][2] *= fac1; oacc[dt][3] *= fac1;
            }

            asm volatile("cp.async.wait_group 1;" ::: "memory");   // V(kt)
            __syncthreads();

            // ---- O_partial += P V over warp's 64 k-rows ----
#pragma unroll
            for (int ks = 0; ks < 4; ks++) {
                float* s0 = sacc[ks * 2];
                float* s1 = sacc[ks * 2 + 1];
                uint32_t pa[4];
                pa[0] = pack_h2(s0[0], s0[1]);
                pa[1] = pack_h2(s0[2], s0[3]);
                pa[2] = pack_h2(s1[0], s1[1]);
                pa[3] = pack_h2(s1[2], s1[3]);
#pragma unroll
                for (int dt = 0; dt < 8; dt++) {
                    uint32_t vH[4];
                    ldm_x4_t(vH, sb + OFF_V + (uint32_t)((wn * 64 + ks * 16) * RSTR) + laneA + dt * 32);
                    mma_f16(oacc[dt * 2],     pa, vH[0], vH[1]);
                    mma_f16(oacc[dt * 2 + 1], pa, vH[2], vH[3]);
                }
            }
            __syncthreads();   // done reading V

            {   // prefetch next V (skipped work on last iter, commit kept)
                if (kt + 1 < nkt)
                    load128(sb + OFF_V, g_Vf + ((size_t)b * T_ + (kt + 1) * 128) * HS_);
                asm volatile("cp.async.commit_group;");
            }
        }

        asm volatile("cp.async.wait_group 0;" ::: "memory");
        __syncthreads();

        // ---- combine the two wn-halves (m,l,O) and store ----
        if (wn == 1) {
#pragma unroll
            for (int dt = 0; dt < 16; dt++) {
                const int c = dt * 8 + tg * 2;
                Ocmb[rloc0 * OCSTR + c]           = oacc[dt][0];
                Ocmb[rloc0 * OCSTR + c + 1]       = oacc[dt][1];
                Ocmb[(rloc0 + 8) * OCSTR + c]     = oacc[dt][2];
                Ocmb[(rloc0 + 8) * OCSTR + c + 1] = oacc[dt][3];
            }
            if (tg == 0) {
                sMax[rloc0] = m0_;   sSum[rloc0] = l0_;
                sMax[rloc0 + 8] = m1_; sSum[rloc0 + 8] = l1_;
            }
        }
        __syncthreads();
        if (wn == 0) {
            const float mo0 = sMax[rloc0], mo1 = sMax[rloc0 + 8];
            const float mf0 = fmaxf(m0_, mo0), mf1 = fmaxf(m1_, mo1);
            const float a0 = __expf(m0_ - mf0), b0f = __expf(mo0 - mf0);
            const float a1 = __expf(m1_ - mf1), b1f = __expf(mo1 - mf1);
            const float inv0 = 1.0f / (l0_ * a0 + sSum[rloc0] * b0f);
            const float inv1 = 1.0f / (l1_ * a1 + sSum[rloc0 + 8] * b1f);
            float* y0 = y + ((size_t)b * T_ + qbase + rloc0) * HS_;
            float* y1 = y0 + 8 * HS_;
#pragma unroll
            for (int dt = 0; dt < 16; dt++) {
                const int c = dt * 8 + tg * 2;
                float r0 = (oacc[dt][0] * a0 + Ocmb[rloc0 * OCSTR + c] * b0f) * inv0;
                float r1 = (oacc[dt][1] * a0 + Ocmb[rloc0 * OCSTR + c + 1] * b0f) * inv0;
                float r2 = (oacc[dt][2] * a1 + Ocmb[(rloc0 + 8) * OCSTR + c] * b1f) * inv1;
                float r3 = (oacc[dt][3] * a1 + Ocmb[(rloc0 + 8) * OCSTR + c + 1] * b1f) * inv1;
                *(float2*)(y0 + c) = make_float2(r0, r1);
                *(float2*)(y1 + c) = make_float2(r2, r3);
            }
        }
        __syncthreads();   // protect smem reuse for next q-tile
    }
}

// ---------------------------------------------------------------------------
extern "C" void kernel_launch(void* const* d_in, const int* in_sizes, int n_in,
                              void* d_out, int out_size)
{
    const float* x  = (const float*)d_in[0];
    const float* Wq = (const float*)d_in[1];
    const float* Wk = (const float*)d_in[2];
    const float* Wv = (const float*)d_in[3];
    float* y = (float*)d_out;
    (void)in_sizes; (void)n_in; (void)out_size;

    prep_w<<<dim3(64, 4, 3), 256>>>(Wq, Wk, Wv);

    cudaFuncSetAttribute(qkv_mma, cudaFuncAttributeMaxDynamicSharedMemorySize, SMEM_QKV);
    qkv_mma<<<dim3(3, 128), 256, SMEM_QKV>>>(x);

    cudaFuncSetAttribute(flash_mma, cudaFuncAttributeMaxDynamicSharedMemorySize, SMEM_FL);
    flash_mma<<<dim3(32, 4), 256, SMEM_FL>>>(y);
}